// round 3
// baseline (speedup 1.0000x reference)
#include <cuda_runtime.h>
#include <math.h>

#define NUSER 100000
#define NITEM 50000
#define NENT  200000
#define NREL  32
#define D     64
#define NEDGE 500000
#define NNZ   2000000
#define NUI   (NUSER + NITEM)
#define FULL  0xffffffffu

// ---------------- scratch (device globals; no runtime allocation) ----------
__device__ float g_sA[NENT * D];     // hop1 output
__device__ float g_sB[NENT * D];     // hop2 output
__device__ float g_A[NUI * D];       // embeds
__device__ float g_B[NUI * D];       // gcn intermediate
// edge CSR (by head)
__device__ int   g_ecnt[NENT];
__device__ int   g_eptr[NENT + 1];
__device__ int   g_ecur[NENT];
__device__ int   g_etr [NEDGE];      // packed tail | (rtype<<18)
// adj CSR (by row)
__device__ int   g_acnt[NUI];
__device__ int   g_aptr[NUI + 1];
__device__ int   g_acur[NUI];
__device__ int   g_acol[NNZ];
__device__ float g_aval[NNZ];
__device__ int   g_bsums[1024];

// ---------------- helpers ----------------
__device__ __forceinline__ float wredsum(float v) {
    v += __shfl_xor_sync(FULL, v, 16);
    v += __shfl_xor_sync(FULL, v, 8);
    v += __shfl_xor_sync(FULL, v, 4);
    v += __shfl_xor_sync(FULL, v, 2);
    v += __shfl_xor_sync(FULL, v, 1);
    return v;
}
__device__ __forceinline__ float tanhf_fast(float x) {  // x >= 0
    if (x < 1e-4f) return x;
    float e = __expf(2.0f * x);
    return __fdividef(e - 1.0f, e + 1.0f);
}
__device__ __forceinline__ float atanhf_fast(float x) { // 0 <= x <= 1-1e-5
    return 0.5f * __logf(__fdividef(1.0f + x, 1.0f - x));
}

// ---------------- generic hist / scan / scatter for CSR builds -------------
__global__ void k_hist(const int* __restrict__ key, int n, int* __restrict__ cnt) {
    int i = blockIdx.x * blockDim.x + threadIdx.x;
    if (i < n) atomicAdd(&cnt[key[i]], 1);
}
__global__ void k_blocksum(const int* __restrict__ cnt, int n, int* __restrict__ bs) {
    __shared__ int sh[1024];
    int i = blockIdx.x * 1024 + threadIdx.x;
    sh[threadIdx.x] = (i < n) ? cnt[i] : 0;
    __syncthreads();
    for (int s = 512; s > 0; s >>= 1) {
        if (threadIdx.x < s) sh[threadIdx.x] += sh[threadIdx.x + s];
        __syncthreads();
    }
    if (threadIdx.x == 0) bs[blockIdx.x] = sh[0];
}
__global__ void k_scanbsums(int* __restrict__ bs, int nb) {
    __shared__ int sh[1024];
    int v = (threadIdx.x < nb) ? bs[threadIdx.x] : 0;
    sh[threadIdx.x] = v;
    __syncthreads();
    for (int off = 1; off < 1024; off <<= 1) {
        int t = (threadIdx.x >= off) ? sh[threadIdx.x - off] : 0;
        __syncthreads();
        sh[threadIdx.x] += t;
        __syncthreads();
    }
    if (threadIdx.x < nb) bs[threadIdx.x] = sh[threadIdx.x] - v;  // exclusive
}
__global__ void k_scanblock(const int* __restrict__ cnt, int n,
                            const int* __restrict__ bs,
                            int* __restrict__ ptr, int* __restrict__ cur) {
    __shared__ int sh[1024];
    int i = blockIdx.x * 1024 + threadIdx.x;
    int v = (i < n) ? cnt[i] : 0;
    sh[threadIdx.x] = v;
    __syncthreads();
    for (int off = 1; off < 1024; off <<= 1) {
        int t = (threadIdx.x >= off) ? sh[threadIdx.x - off] : 0;
        __syncthreads();
        sh[threadIdx.x] += t;
        __syncthreads();
    }
    int excl = sh[threadIdx.x] - v + bs[blockIdx.x];
    if (i < n) { ptr[i] = excl; cur[i] = excl; }
    if (i == n - 1) ptr[n] = excl + v;
}
__global__ void k_escatter(const int* __restrict__ head, const int* __restrict__ tail,
                           const int* __restrict__ etype,
                           int* __restrict__ cur, int* __restrict__ etr) {
    int i = blockIdx.x * blockDim.x + threadIdx.x;
    if (i >= NEDGE) return;
    int pos = atomicAdd(&cur[head[i]], 1);
    etr[pos] = tail[i] | ((etype[i] - 1) << 18);
}
__global__ void k_ascatter(const int* __restrict__ row, const int* __restrict__ col,
                           const float* __restrict__ val,
                           int* __restrict__ cur,
                           int* __restrict__ ocol, float* __restrict__ oval) {
    int i = blockIdx.x * blockDim.x + threadIdx.x;
    if (i >= NNZ) return;
    int pos = atomicAdd(&cur[row[i]], 1);
    ocol[pos] = col[i];
    oval[pos] = val[i];
}

// ---------------- RGAT hop: warp per head, fused mean+l2norm ---------------
__global__ void __launch_bounds__(256) k_hop(
    const float* __restrict__ ent, const float* __restrict__ rel,
    const int* __restrict__ eptr, const int* __restrict__ etr,
    float* __restrict__ outEnt)
{
    __shared__ float s_rel[NREL * D];
    __shared__ float s_relC[NREL];
    for (int i = threadIdx.x; i < NREL * D; i += blockDim.x) s_rel[i] = rel[i];
    __syncthreads();
    if (threadIdx.x < NREL) {
        float s = 0.0f;
        #pragma unroll 8
        for (int k = 0; k < D; k++) { float v = s_rel[threadIdx.x * D + k]; s += v * v; }
        s_relC[threadIdx.x] = s;
    }
    __syncthreads();

    int w = (blockIdx.x * blockDim.x + threadIdx.x) >> 5;   // head id, exact grid
    int lane = threadIdx.x & 31;
    int beg = eptr[w], end = eptr[w + 1];

    const float2* e2 = reinterpret_cast<const float2*>(ent);
    const float2* r2 = reinterpret_cast<const float2*>(s_rel);
    float2 acc = make_float2(0.0f, 0.0f);

    if (beg < end) {
        const float MINN = 1e-15f;
        float2 he = e2[(size_t)w * 32 + lane];
        float A = wredsum(he.x * he.x + he.y * he.y);
        // per-head scalars (hh = alpha * he)
        float nhe   = fmaxf(sqrtf(A), MINN);
        float alpha = __fdividef(tanhf_fast(nhe), nhe);
        float sq    = alpha * alpha * A;
        float omq   = 1.0f - sq;
        float lamden = fmaxf(omq, MINN);
        float lam   = __fdividef(2.0f, lamden);

        for (int i = beg; i < end; i++) {
            int pk = etr[i];
            int t = pk & 0x3ffff;
            int r = pk >> 18;
            float2 te = e2[(size_t)t * 32 + lane];
            float2 re = r2[r * 32 + lane];
            float C = s_relC[r];
            float B = wredsum(te.x * te.x + te.y * te.y);
            float P = wredsum(he.x * te.x + he.y * te.y);
            float Q = wredsum(he.x * re.x + he.y * re.y);
            float R = wredsum(te.x * re.x + te.y * re.y);

            // ht = expmap(te, hh) = p1*he + p2*te
            float nte = fmaxf(sqrtf(B), MINN);
            float at  = __fdividef(tanhf_fast(0.5f * lam * nte), nte);
            float y2t = at * at * B;
            float xyt = at * alpha * P;
            float dent = fmaxf(1.0f + 2.0f * xyt + sq * y2t, MINN);
            float p1 = __fdividef((1.0f + 2.0f * xyt + y2t) * alpha, dent);
            float p2 = __fdividef(omq * at, dent);
            // hr = expmap(re, hh) = q1*he + q3*re
            float nre = fmaxf(sqrtf(C), MINN);
            float ar  = __fdividef(tanhf_fast(0.5f * lam * nre), nre);
            float y2r = ar * ar * C;
            float xyr = ar * alpha * Q;
            float denr = fmaxf(1.0f + 2.0f * xyr + sq * y2r, MINN);
            float q1 = __fdividef((1.0f + 2.0f * xyr + y2r) * alpha, denr);
            float q3 = __fdividef(omq * ar, denr);
            // scalar dots
            float sht = p1 * p1 * A + 2.0f * p1 * p2 * P + p2 * p2 * B;
            float shr = q1 * q1 * A + 2.0f * q1 * q3 * Q + q3 * q3 * C;
            float dhh = p1 * q1 * A + p1 * q3 * Q + p2 * q1 * P + p2 * q3 * R;
            // m = mobius_add(ht, hr) = m1*he + m2*te + m3*re
            float denm = fmaxf(1.0f + 2.0f * dhh + sht * shr, MINN);
            float f1 = __fdividef(1.0f + 2.0f * dhh + shr, denm);
            float f2 = __fdividef(1.0f - sht, denm);
            float m1 = f1 * p1 + f2 * q1;
            float m2 = f1 * p2;
            float m3 = f2 * q3;
            float sm = m1 * m1 * A + m2 * m2 * B + m3 * m3 * C
                     + 2.0f * (m1 * m2 * P + m1 * m3 * Q + m2 * m3 * R);
            sm = fmaxf(sm, 0.0f);
            // project
            float nm = fmaxf(sqrtf(sm), MINN);
            float scale = (nm > 0.999f) ? __fdividef(0.999f, nm) : 1.0f;
            float sqres = sm * scale * scale;
            // logmap: sub = u1*he + u2*te + u3*re
            float dhres = scale * alpha * (m1 * A + m2 * P + m3 * Q);
            float xy = -dhres;
            float denl = fmaxf(1.0f + 2.0f * xy + sq * sqres, MINN);
            float gg1 = __fdividef(1.0f + 2.0f * xy + sqres, denl);
            float gg2 = __fdividef(omq, denl);
            float u1 = -gg1 * alpha + gg2 * scale * m1;
            float u2 = gg2 * scale * m2;
            float u3 = gg2 * scale * m3;
            float ssub = u1 * u1 * A + u2 * u2 * B + u3 * u3 * C
                       + 2.0f * (u1 * u2 * P + u1 * u3 * Q + u2 * u3 * R);
            ssub = fmaxf(ssub, 0.0f);
            float nsub = fmaxf(sqrtf(ssub), MINN);
            float coef = lamden * __fdividef(atanhf_fast(fminf(nsub, 1.0f - 1e-5f)), nsub);
            // ricci coefficient
            float stere = B + 2.0f * R + C;
            float epst = __fdividef(1e-7f, fmaxf(sqrtf(stere), 1e-12f));

            float c1 = coef * u1;
            float c2 = coef * u2 + epst;
            float c3 = coef * u3 + epst;

            acc.x += fmaxf(c1 * he.x + c2 * te.x + c3 * re.x, 0.0f);
            acc.y += fmaxf(c1 * he.y + c2 * te.y + c3 * re.y, 0.0f);
        }
        // mean is scale-invariant under l2norm; fuse l2norm directly
        float s = wredsum(acc.x * acc.x + acc.y * acc.y);
        float inv = __fdividef(1.0f, fmaxf(sqrtf(s), 1e-12f));
        acc.x *= inv; acc.y *= inv;
    }
    reinterpret_cast<float2*>(outEnt)[(size_t)w * 32 + lane] = acc;
}

// ---------------- embeds = concat(u, 0.25*e0 + 0.5*n1 + n2) ----------------
__global__ void __launch_bounds__(256) k_embeds(
    const float* __restrict__ u, const float* __restrict__ e0,
    const float* __restrict__ n1, const float* __restrict__ n2,
    float* __restrict__ Aout, float* __restrict__ out)
{
    int i = blockIdx.x * blockDim.x + threadIdx.x;  // float2 index, exact grid
    int row = i >> 5;
    float2 v;
    if (row < NUSER) {
        v = reinterpret_cast<const float2*>(u)[i];
    } else {
        int j = i - NUSER * 32;
        float2 a = reinterpret_cast<const float2*>(e0)[j];
        float2 b = reinterpret_cast<const float2*>(n1)[j];
        float2 c = reinterpret_cast<const float2*>(n2)[j];
        v.x = 0.25f * a.x + 0.5f * b.x + c.x;
        v.y = 0.25f * a.y + 0.5f * b.y + c.y;
    }
    reinterpret_cast<float2*>(Aout)[i] = v;
    reinterpret_cast<float2*>(out)[i] = v;
}

// ---------------- CSR SpMM: warp per row, uniform loads, fused out += ------
template <int STORE>
__global__ void __launch_bounds__(256) k_spmm(
    const float* __restrict__ curbuf, const int* __restrict__ ptr,
    const int* __restrict__ cols, const float* __restrict__ vals,
    float* __restrict__ nxt, float* __restrict__ out)
{
    int w = (blockIdx.x * blockDim.x + threadIdx.x) >> 5;
    int lane = threadIdx.x & 31;
    int beg = ptr[w], end = ptr[w + 1];
    const float2* c2 = reinterpret_cast<const float2*>(curbuf);
    float2 acc = make_float2(0.0f, 0.0f);
    int j = beg;
    for (; j + 4 <= end; j += 4) {
        int   c0 = cols[j],     c1 = cols[j + 1], c2i = cols[j + 2], c3 = cols[j + 3];
        float v0 = vals[j],     v1 = vals[j + 1], v2 = vals[j + 2],  v3 = vals[j + 3];
        float2 x0 = c2[(size_t)c0  * 32 + lane];
        float2 x1 = c2[(size_t)c1  * 32 + lane];
        float2 x2 = c2[(size_t)c2i * 32 + lane];
        float2 x3 = c2[(size_t)c3  * 32 + lane];
        acc.x = fmaf(v0, x0.x, acc.x); acc.y = fmaf(v0, x0.y, acc.y);
        acc.x = fmaf(v1, x1.x, acc.x); acc.y = fmaf(v1, x1.y, acc.y);
        acc.x = fmaf(v2, x2.x, acc.x); acc.y = fmaf(v2, x2.y, acc.y);
        acc.x = fmaf(v3, x3.x, acc.x); acc.y = fmaf(v3, x3.y, acc.y);
    }
    for (; j < end; j++) {
        int cc = cols[j]; float vv = vals[j];
        float2 x = c2[(size_t)cc * 32 + lane];
        acc.x = fmaf(vv, x.x, acc.x);
        acc.y = fmaf(vv, x.y, acc.y);
    }
    size_t o = (size_t)w * 32 + lane;
    if (STORE) reinterpret_cast<float2*>(nxt)[o] = acc;
    float2 ov = reinterpret_cast<float2*>(out)[o];
    ov.x += acc.x; ov.y += acc.y;
    reinterpret_cast<float2*>(out)[o] = ov;
}

// ---------------- launch ---------------------------------------------------
extern "C" void kernel_launch(void* const* d_in, const int* in_sizes, int n_in,
                              void* d_out, int out_size)
{
    const float* uE   = (const float*)d_in[0];
    const float* eE   = (const float*)d_in[1];
    const float* rE   = (const float*)d_in[2];
    const float* aval = (const float*)d_in[3];
    const int*   eh   = (const int*)d_in[4];
    const int*   et   = (const int*)d_in[5];
    const int*   ety  = (const int*)d_in[6];
    const int*   arow = (const int*)d_in[7];
    const int*   acol = (const int*)d_in[8];
    float* out = (float*)d_out;

    float *sA, *sB, *A, *B, *avalS;
    int *ecnt, *eptr, *ecur, *etr;
    int *acnt, *aptr, *acur, *acolS, *bsums;
    cudaGetSymbolAddress((void**)&sA,    g_sA);
    cudaGetSymbolAddress((void**)&sB,    g_sB);
    cudaGetSymbolAddress((void**)&A,     g_A);
    cudaGetSymbolAddress((void**)&B,     g_B);
    cudaGetSymbolAddress((void**)&ecnt,  g_ecnt);
    cudaGetSymbolAddress((void**)&eptr,  g_eptr);
    cudaGetSymbolAddress((void**)&ecur,  g_ecur);
    cudaGetSymbolAddress((void**)&etr,   g_etr);
    cudaGetSymbolAddress((void**)&acnt,  g_acnt);
    cudaGetSymbolAddress((void**)&aptr,  g_aptr);
    cudaGetSymbolAddress((void**)&acur,  g_acur);
    cudaGetSymbolAddress((void**)&acolS, g_acol);
    cudaGetSymbolAddress((void**)&avalS, g_aval);
    cudaGetSymbolAddress((void**)&bsums, g_bsums);

    const int nbE = (NENT + 1023) / 1024;  // 196
    const int nbA = (NUI + 1023) / 1024;   // 147

    // ---- edge CSR build (grouped by head) — reused by both hops
    cudaMemsetAsync(ecnt, 0, NENT * sizeof(int));
    k_hist<<<(NEDGE + 255) / 256, 256>>>(eh, NEDGE, ecnt);
    k_blocksum<<<nbE, 1024>>>(ecnt, NENT, bsums);
    k_scanbsums<<<1, 1024>>>(bsums, nbE);
    k_scanblock<<<nbE, 1024>>>(ecnt, NENT, bsums, eptr, ecur);
    k_escatter<<<(NEDGE + 255) / 256, 256>>>(eh, et, ety, ecur, etr);

    // ---- RGAT hops (warp per head, fused norm)
    k_hop<<<NENT / 8, 256>>>(eE, rE, eptr, etr, sA);
    k_hop<<<NENT / 8, 256>>>(sA, rE, eptr, etr, sB);

    // ---- adj CSR build
    cudaMemsetAsync(acnt, 0, NUI * sizeof(int));
    k_hist<<<(NNZ + 255) / 256, 256>>>(arow, NNZ, acnt);
    k_blocksum<<<nbA, 1024>>>(acnt, NUI, bsums);
    k_scanbsums<<<1, 1024>>>(bsums, nbA);
    k_scanblock<<<nbA, 1024>>>(acnt, NUI, bsums, aptr, acur);
    k_ascatter<<<(NNZ + 255) / 256, 256>>>(arow, acol, aval, acur, acolS, avalS);

    // ---- embeds + total init (ent_res = 0.25*e0 + 0.5*n1 + n2)
    k_embeds<<<NUI * 32 / 256, 256>>>(uE, eE, sA, sB, A, out);

    // ---- GCN layers via CSR, out += fused
    k_spmm<1><<<NUI / 8, 256>>>(A, aptr, acolS, avalS, B, out);
    k_spmm<0><<<NUI / 8, 256>>>(B, aptr, acolS, avalS, nullptr, out);
}

// round 4
// speedup vs baseline: 1.1695x; 1.1695x over previous
#include <cuda_runtime.h>
#include <math.h>

#define NUSER 100000
#define NITEM 50000
#define NENT  200000
#define NREL  32
#define D     64
#define NEDGE 500000
#define NNZ   2000000
#define NUI   (NUSER + NITEM)
#define FULL  0xffffffffu

// ---------------- scratch (device globals; no runtime allocation) ----------
__device__ float  g_sA[NENT * D];     // hop1 output
__device__ float  g_sB[NENT * D];     // hop2 output
__device__ float  g_A[NUI * D];       // embeds
__device__ float  g_B[NUI * D];       // gcn intermediate
__device__ float4 g_coef[NEDGE];      // per-edge (c1,c2,c3)
// edge CSR (sorted by head)
__device__ int   g_ecnt[NENT];
__device__ int   g_eptr[NENT + 1];
__device__ int   g_ecur[NENT];
__device__ int   g_ehead[NEDGE];      // head per sorted edge
__device__ int   g_etr [NEDGE];       // packed tail | (rtype<<18)
// adj CSR (by row)
__device__ int   g_acnt[NUI];
__device__ int   g_aptr[NUI + 1];
__device__ int   g_acur[NUI];
__device__ int   g_acol[NNZ];
__device__ float g_aval[NNZ];
__device__ int   g_bsums[1024];

// ---------------- helpers ----------------
__device__ __forceinline__ float wredsum(float v) {
    v += __shfl_xor_sync(FULL, v, 16);
    v += __shfl_xor_sync(FULL, v, 8);
    v += __shfl_xor_sync(FULL, v, 4);
    v += __shfl_xor_sync(FULL, v, 2);
    v += __shfl_xor_sync(FULL, v, 1);
    return v;
}
__device__ __forceinline__ float hredsum(float v) {   // 16-lane groups
    v += __shfl_xor_sync(FULL, v, 8);
    v += __shfl_xor_sync(FULL, v, 4);
    v += __shfl_xor_sync(FULL, v, 2);
    v += __shfl_xor_sync(FULL, v, 1);
    return v;
}
__device__ __forceinline__ float dot4(float4 a, float4 b) {
    return a.x * b.x + a.y * b.y + a.z * b.z + a.w * b.w;
}
__device__ __forceinline__ float tanhf_fast(float x) {  // x >= 0
    if (x < 1e-4f) return x;
    float e = __expf(2.0f * x);
    return __fdividef(e - 1.0f, e + 1.0f);
}
__device__ __forceinline__ float atanhf_fast(float x) { // 0 <= x <= 1-1e-5
    return 0.5f * __logf(__fdividef(1.0f + x, 1.0f - x));
}

// ---------------- generic hist / scan for CSR builds -----------------------
__global__ void k_hist(const int* __restrict__ key, int n, int* __restrict__ cnt) {
    int i = blockIdx.x * blockDim.x + threadIdx.x;
    if (i < n) atomicAdd(&cnt[key[i]], 1);
}
__global__ void k_blocksum(const int* __restrict__ cnt, int n, int* __restrict__ bs) {
    __shared__ int sh[1024];
    int i = blockIdx.x * 1024 + threadIdx.x;
    sh[threadIdx.x] = (i < n) ? cnt[i] : 0;
    __syncthreads();
    for (int s = 512; s > 0; s >>= 1) {
        if (threadIdx.x < s) sh[threadIdx.x] += sh[threadIdx.x + s];
        __syncthreads();
    }
    if (threadIdx.x == 0) bs[blockIdx.x] = sh[0];
}
__global__ void k_scanbsums(int* __restrict__ bs, int nb) {
    __shared__ int sh[1024];
    int v = (threadIdx.x < nb) ? bs[threadIdx.x] : 0;
    sh[threadIdx.x] = v;
    __syncthreads();
    for (int off = 1; off < 1024; off <<= 1) {
        int t = (threadIdx.x >= off) ? sh[threadIdx.x - off] : 0;
        __syncthreads();
        sh[threadIdx.x] += t;
        __syncthreads();
    }
    if (threadIdx.x < nb) bs[threadIdx.x] = sh[threadIdx.x] - v;  // exclusive
}
__global__ void k_scanblock(const int* __restrict__ cnt, int n,
                            const int* __restrict__ bs,
                            int* __restrict__ ptr, int* __restrict__ cur) {
    __shared__ int sh[1024];
    int i = blockIdx.x * 1024 + threadIdx.x;
    int v = (i < n) ? cnt[i] : 0;
    sh[threadIdx.x] = v;
    __syncthreads();
    for (int off = 1; off < 1024; off <<= 1) {
        int t = (threadIdx.x >= off) ? sh[threadIdx.x - off] : 0;
        __syncthreads();
        sh[threadIdx.x] += t;
        __syncthreads();
    }
    int excl = sh[threadIdx.x] - v + bs[blockIdx.x];
    if (i < n) { ptr[i] = excl; cur[i] = excl; }
    if (i == n - 1) ptr[n] = excl + v;
}
__global__ void k_escatter(const int* __restrict__ head, const int* __restrict__ tail,
                           const int* __restrict__ etype,
                           int* __restrict__ cur,
                           int* __restrict__ ehead, int* __restrict__ etr) {
    int i = blockIdx.x * blockDim.x + threadIdx.x;
    if (i >= NEDGE) return;
    int h = head[i];
    int pos = atomicAdd(&cur[h], 1);
    ehead[pos] = h;
    etr[pos] = tail[i] | ((etype[i] - 1) << 18);
}
__global__ void k_ascatter(const int* __restrict__ row, const int* __restrict__ col,
                           const float* __restrict__ val,
                           int* __restrict__ cur,
                           int* __restrict__ ocol, float* __restrict__ oval) {
    int i = blockIdx.x * blockDim.x + threadIdx.x;
    if (i >= NNZ) return;
    int pos = atomicAdd(&cur[row[i]], 1);
    ocol[pos] = col[i];
    oval[pos] = val[i];
}

// ---------------- RGAT phase 1: per-edge coefficients (2 edges/warp) -------
__global__ void __launch_bounds__(256) k_coef(
    const float* __restrict__ entP, const float* __restrict__ rel,
    const int* __restrict__ ehead, const int* __restrict__ etr,
    float4* __restrict__ coef)
{
    __shared__ float s_rel[NREL * D];
    __shared__ float s_relC[NREL];
    for (int i = threadIdx.x; i < NREL * D; i += blockDim.x) s_rel[i] = rel[i];
    __syncthreads();
    if (threadIdx.x < NREL) {
        float s = 0.0f;
        #pragma unroll 8
        for (int k = 0; k < D; k++) { float v = s_rel[threadIdx.x * D + k]; s += v * v; }
        s_relC[threadIdx.x] = s;
    }
    __syncthreads();

    int lane = threadIdx.x & 31;
    int half = lane >> 4;
    int sl   = lane & 15;
    int e = ((blockIdx.x * blockDim.x + threadIdx.x) >> 5) * 2 + half;  // exact grid

    int h  = ehead[e];
    int pk = etr[e];
    int t  = pk & 0x3ffff;
    int r  = pk >> 18;

    const float4* e4 = reinterpret_cast<const float4*>(entP);
    float4 he = e4[(size_t)h * 16 + sl];
    float4 te = e4[(size_t)t * 16 + sl];
    float4 re = reinterpret_cast<const float4*>(s_rel)[r * 16 + sl];

    float A = hredsum(dot4(he, he));
    float B = hredsum(dot4(te, te));
    float P = hredsum(dot4(he, te));
    float Q = hredsum(dot4(he, re));
    float R = hredsum(dot4(te, re));
    float C = s_relC[r];

    const float MINN = 1e-15f;
    float nhe   = fmaxf(sqrtf(A), MINN);
    float alpha = __fdividef(tanhf_fast(nhe), nhe);
    float sq    = alpha * alpha * A;
    float omq   = 1.0f - sq;
    float lamden = fmaxf(omq, MINN);
    float lam   = __fdividef(2.0f, lamden);
    // ht = p1*he + p2*te
    float nte = fmaxf(sqrtf(B), MINN);
    float at  = __fdividef(tanhf_fast(0.5f * lam * nte), nte);
    float y2t = at * at * B;
    float xyt = at * alpha * P;
    float dent = fmaxf(1.0f + 2.0f * xyt + sq * y2t, MINN);
    float p1 = __fdividef((1.0f + 2.0f * xyt + y2t) * alpha, dent);
    float p2 = __fdividef(omq * at, dent);
    // hr = q1*he + q3*re
    float nre = fmaxf(sqrtf(C), MINN);
    float ar  = __fdividef(tanhf_fast(0.5f * lam * nre), nre);
    float y2r = ar * ar * C;
    float xyr = ar * alpha * Q;
    float denr = fmaxf(1.0f + 2.0f * xyr + sq * y2r, MINN);
    float q1 = __fdividef((1.0f + 2.0f * xyr + y2r) * alpha, denr);
    float q3 = __fdividef(omq * ar, denr);
    // scalar dots
    float sht = p1 * p1 * A + 2.0f * p1 * p2 * P + p2 * p2 * B;
    float shr = q1 * q1 * A + 2.0f * q1 * q3 * Q + q3 * q3 * C;
    float dhh = p1 * q1 * A + p1 * q3 * Q + p2 * q1 * P + p2 * q3 * R;
    // m = m1*he + m2*te + m3*re
    float denm = fmaxf(1.0f + 2.0f * dhh + sht * shr, MINN);
    float f1 = __fdividef(1.0f + 2.0f * dhh + shr, denm);
    float f2 = __fdividef(1.0f - sht, denm);
    float m1 = f1 * p1 + f2 * q1;
    float m2 = f1 * p2;
    float m3 = f2 * q3;
    float sm = m1 * m1 * A + m2 * m2 * B + m3 * m3 * C
             + 2.0f * (m1 * m2 * P + m1 * m3 * Q + m2 * m3 * R);
    sm = fmaxf(sm, 0.0f);
    // project
    float nm = fmaxf(sqrtf(sm), MINN);
    float scale = (nm > 0.999f) ? __fdividef(0.999f, nm) : 1.0f;
    float sqres = sm * scale * scale;
    // logmap: sub = u1*he + u2*te + u3*re
    float dhres = scale * alpha * (m1 * A + m2 * P + m3 * Q);
    float xy = -dhres;
    float denl = fmaxf(1.0f + 2.0f * xy + sq * sqres, MINN);
    float gg1 = __fdividef(1.0f + 2.0f * xy + sqres, denl);
    float gg2 = __fdividef(omq, denl);
    float u1 = -gg1 * alpha + gg2 * scale * m1;
    float u2 = gg2 * scale * m2;
    float u3 = gg2 * scale * m3;
    float ssub = u1 * u1 * A + u2 * u2 * B + u3 * u3 * C
               + 2.0f * (u1 * u2 * P + u1 * u3 * Q + u2 * u3 * R);
    ssub = fmaxf(ssub, 0.0f);
    float nsub = fmaxf(sqrtf(ssub), MINN);
    float coefc = lamden * __fdividef(atanhf_fast(fminf(nsub, 1.0f - 1e-5f)), nsub);
    float stere = B + 2.0f * R + C;
    float epst = __fdividef(1e-7f, fmaxf(sqrtf(stere), 1e-12f));

    if (sl == 0)
        coef[e] = make_float4(coefc * u1, coefc * u2 + epst, coefc * u3 + epst, 0.0f);
}

// ---------------- RGAT phase 2: warp per head, light loop, fused l2norm ----
__global__ void __launch_bounds__(256) k_sumhop(
    const float* __restrict__ ent, const float* __restrict__ rel,
    const int* __restrict__ eptr, const int* __restrict__ etr,
    const float4* __restrict__ coef,
    float* __restrict__ outEnt)
{
    __shared__ float s_rel[NREL * D];
    for (int i = threadIdx.x; i < NREL * D; i += blockDim.x) s_rel[i] = rel[i];
    __syncthreads();

    int w = (blockIdx.x * blockDim.x + threadIdx.x) >> 5;   // head id, exact grid
    int lane = threadIdx.x & 31;
    int beg = eptr[w], end = eptr[w + 1];

    const float2* e2 = reinterpret_cast<const float2*>(ent);
    const float2* r2 = reinterpret_cast<const float2*>(s_rel);
    float2 acc = make_float2(0.0f, 0.0f);

    if (beg < end) {
        float2 he = e2[(size_t)w * 32 + lane];
        int i = beg;
        for (; i + 2 <= end; i += 2) {
            int pk0 = etr[i],     pk1 = etr[i + 1];
            float4 c0 = coef[i];
            float4 c1 = coef[i + 1];
            float2 te0 = e2[(size_t)(pk0 & 0x3ffff) * 32 + lane];
            float2 te1 = e2[(size_t)(pk1 & 0x3ffff) * 32 + lane];
            float2 re0 = r2[(pk0 >> 18) * 32 + lane];
            float2 re1 = r2[(pk1 >> 18) * 32 + lane];
            acc.x += fmaxf(c0.x * he.x + c0.y * te0.x + c0.z * re0.x, 0.0f);
            acc.y += fmaxf(c0.x * he.y + c0.y * te0.y + c0.z * re0.y, 0.0f);
            acc.x += fmaxf(c1.x * he.x + c1.y * te1.x + c1.z * re1.x, 0.0f);
            acc.y += fmaxf(c1.x * he.y + c1.y * te1.y + c1.z * re1.y, 0.0f);
        }
        if (i < end) {
            int pk0 = etr[i];
            float4 c0 = coef[i];
            float2 te0 = e2[(size_t)(pk0 & 0x3ffff) * 32 + lane];
            float2 re0 = r2[(pk0 >> 18) * 32 + lane];
            acc.x += fmaxf(c0.x * he.x + c0.y * te0.x + c0.z * re0.x, 0.0f);
            acc.y += fmaxf(c0.x * he.y + c0.y * te0.y + c0.z * re0.y, 0.0f);
        }
        // mean is scale-invariant under l2norm; fuse l2norm directly
        float s = wredsum(acc.x * acc.x + acc.y * acc.y);
        float inv = __fdividef(1.0f, fmaxf(sqrtf(s), 1e-12f));
        acc.x *= inv; acc.y *= inv;
    }
    reinterpret_cast<float2*>(outEnt)[(size_t)w * 32 + lane] = acc;
}

// ---------------- embeds = concat(u, 0.25*e0 + 0.5*n1 + n2) ----------------
__global__ void __launch_bounds__(256) k_embeds(
    const float* __restrict__ u, const float* __restrict__ e0,
    const float* __restrict__ n1, const float* __restrict__ n2,
    float* __restrict__ Aout, float* __restrict__ out)
{
    int i = blockIdx.x * blockDim.x + threadIdx.x;  // float2 index, exact grid
    int row = i >> 5;
    float2 v;
    if (row < NUSER) {
        v = reinterpret_cast<const float2*>(u)[i];
    } else {
        int j = i - NUSER * 32;
        float2 a = reinterpret_cast<const float2*>(e0)[j];
        float2 b = reinterpret_cast<const float2*>(n1)[j];
        float2 c = reinterpret_cast<const float2*>(n2)[j];
        v.x = 0.25f * a.x + 0.5f * b.x + c.x;
        v.y = 0.25f * a.y + 0.5f * b.y + c.y;
    }
    reinterpret_cast<float2*>(Aout)[i] = v;
    reinterpret_cast<float2*>(out)[i] = v;
}

// ---------------- CSR SpMM: warp per row, uniform loads, fused out += ------
template <int STORE>
__global__ void __launch_bounds__(256) k_spmm(
    const float* __restrict__ curbuf, const int* __restrict__ ptr,
    const int* __restrict__ cols, const float* __restrict__ vals,
    float* __restrict__ nxt, float* __restrict__ out)
{
    int w = (blockIdx.x * blockDim.x + threadIdx.x) >> 5;
    int lane = threadIdx.x & 31;
    int beg = ptr[w], end = ptr[w + 1];
    const float2* c2 = reinterpret_cast<const float2*>(curbuf);
    float2 acc = make_float2(0.0f, 0.0f);
    int j = beg;
    for (; j + 4 <= end; j += 4) {
        int   c0 = cols[j],     c1 = cols[j + 1], c2i = cols[j + 2], c3 = cols[j + 3];
        float v0 = vals[j],     v1 = vals[j + 1], v2 = vals[j + 2],  v3 = vals[j + 3];
        float2 x0 = c2[(size_t)c0  * 32 + lane];
        float2 x1 = c2[(size_t)c1  * 32 + lane];
        float2 x2 = c2[(size_t)c2i * 32 + lane];
        float2 x3 = c2[(size_t)c3  * 32 + lane];
        acc.x = fmaf(v0, x0.x, acc.x); acc.y = fmaf(v0, x0.y, acc.y);
        acc.x = fmaf(v1, x1.x, acc.x); acc.y = fmaf(v1, x1.y, acc.y);
        acc.x = fmaf(v2, x2.x, acc.x); acc.y = fmaf(v2, x2.y, acc.y);
        acc.x = fmaf(v3, x3.x, acc.x); acc.y = fmaf(v3, x3.y, acc.y);
    }
    for (; j < end; j++) {
        int cc = cols[j]; float vv = vals[j];
        float2 x = c2[(size_t)cc * 32 + lane];
        acc.x = fmaf(vv, x.x, acc.x);
        acc.y = fmaf(vv, x.y, acc.y);
    }
    size_t o = (size_t)w * 32 + lane;
    if (STORE) reinterpret_cast<float2*>(nxt)[o] = acc;
    float2 ov = reinterpret_cast<float2*>(out)[o];
    ov.x += acc.x; ov.y += acc.y;
    reinterpret_cast<float2*>(out)[o] = ov;
}

// ---------------- launch ---------------------------------------------------
extern "C" void kernel_launch(void* const* d_in, const int* in_sizes, int n_in,
                              void* d_out, int out_size)
{
    const float* uE   = (const float*)d_in[0];
    const float* eE   = (const float*)d_in[1];
    const float* rE   = (const float*)d_in[2];
    const float* aval = (const float*)d_in[3];
    const int*   eh   = (const int*)d_in[4];
    const int*   et   = (const int*)d_in[5];
    const int*   ety  = (const int*)d_in[6];
    const int*   arow = (const int*)d_in[7];
    const int*   acol = (const int*)d_in[8];
    float* out = (float*)d_out;

    float *sA, *sB, *A, *B, *avalS;
    float4* coef;
    int *ecnt, *eptr, *ecur, *ehead, *etr;
    int *acnt, *aptr, *acur, *acolS, *bsums;
    cudaGetSymbolAddress((void**)&sA,    g_sA);
    cudaGetSymbolAddress((void**)&sB,    g_sB);
    cudaGetSymbolAddress((void**)&A,     g_A);
    cudaGetSymbolAddress((void**)&B,     g_B);
    cudaGetSymbolAddress((void**)&coef,  g_coef);
    cudaGetSymbolAddress((void**)&ecnt,  g_ecnt);
    cudaGetSymbolAddress((void**)&eptr,  g_eptr);
    cudaGetSymbolAddress((void**)&ecur,  g_ecur);
    cudaGetSymbolAddress((void**)&ehead, g_ehead);
    cudaGetSymbolAddress((void**)&etr,   g_etr);
    cudaGetSymbolAddress((void**)&acnt,  g_acnt);
    cudaGetSymbolAddress((void**)&aptr,  g_aptr);
    cudaGetSymbolAddress((void**)&acur,  g_acur);
    cudaGetSymbolAddress((void**)&acolS, g_acol);
    cudaGetSymbolAddress((void**)&avalS, g_aval);
    cudaGetSymbolAddress((void**)&bsums, g_bsums);

    const int nbE = (NENT + 1023) / 1024;  // 196
    const int nbA = (NUI + 1023) / 1024;   // 147

    // ---- edge CSR build (sorted by head) — reused by both hops
    cudaMemsetAsync(ecnt, 0, NENT * sizeof(int));
    k_hist<<<(NEDGE + 255) / 256, 256>>>(eh, NEDGE, ecnt);
    k_blocksum<<<nbE, 1024>>>(ecnt, NENT, bsums);
    k_scanbsums<<<1, 1024>>>(bsums, nbE);
    k_scanblock<<<nbE, 1024>>>(ecnt, NENT, bsums, eptr, ecur);
    k_escatter<<<(NEDGE + 255) / 256, 256>>>(eh, et, ety, ecur, ehead, etr);

    // ---- RGAT hop 1
    k_coef<<<NEDGE / 16, 256>>>(eE, rE, ehead, etr, coef);
    k_sumhop<<<NENT / 8, 256>>>(eE, rE, eptr, etr, coef, sA);
    // ---- RGAT hop 2
    k_coef<<<NEDGE / 16, 256>>>(sA, rE, ehead, etr, coef);
    k_sumhop<<<NENT / 8, 256>>>(sA, rE, eptr, etr, coef, sB);

    // ---- adj CSR build
    cudaMemsetAsync(acnt, 0, NUI * sizeof(int));
    k_hist<<<(NNZ + 255) / 256, 256>>>(arow, NNZ, acnt);
    k_blocksum<<<nbA, 1024>>>(acnt, NUI, bsums);
    k_scanbsums<<<1, 1024>>>(bsums, nbA);
    k_scanblock<<<nbA, 1024>>>(acnt, NUI, bsums, aptr, acur);
    k_ascatter<<<(NNZ + 255) / 256, 256>>>(arow, acol, aval, acur, acolS, avalS);

    // ---- embeds + total init (ent_res = 0.25*e0 + 0.5*n1 + n2)
    k_embeds<<<NUI * 32 / 256, 256>>>(uE, eE, sA, sB, A, out);

    // ---- GCN layers via CSR, out += fused
    k_spmm<1><<<NUI / 8, 256>>>(A, aptr, acolS, avalS, B, out);
    k_spmm<0><<<NUI / 8, 256>>>(B, aptr, acolS, avalS, nullptr, out);
}

// round 5
// speedup vs baseline: 1.3238x; 1.1319x over previous
#include <cuda_runtime.h>
#include <math.h>

#define NUSER 100000
#define NITEM 50000
#define NENT  200000
#define NREL  32
#define D     64
#define NEDGE 500000
#define NNZ   2000000
#define NUI   (NUSER + NITEM)
#define FULL  0xffffffffu

// ---------------- scratch (device globals; no runtime allocation) ----------
__device__ float g_sA[NENT * D];    // hop1 sums -> ent1 (in-place post)
__device__ float g_sB[NENT * D];    // hop2 sums -> ent2
__device__ float g_A[NUI * D];      // embeds
__device__ float g_B[NUI * D];      // gcn intermediate
__device__ int   g_acnt[NUI];
__device__ int   g_aptr[NUI + 1];
__device__ int   g_acur[NUI];
__device__ int   g_acol[NNZ];
__device__ float g_aval[NNZ];
__device__ int   g_bsums[1024];

// ---------------- helpers ----------------
__device__ __forceinline__ float wredsum(float v) {
    v += __shfl_xor_sync(FULL, v, 16);
    v += __shfl_xor_sync(FULL, v, 8);
    v += __shfl_xor_sync(FULL, v, 4);
    v += __shfl_xor_sync(FULL, v, 2);
    v += __shfl_xor_sync(FULL, v, 1);
    return v;
}
__device__ __forceinline__ float hredsum(float v) {   // 16-lane groups
    v += __shfl_xor_sync(FULL, v, 8);
    v += __shfl_xor_sync(FULL, v, 4);
    v += __shfl_xor_sync(FULL, v, 2);
    v += __shfl_xor_sync(FULL, v, 1);
    return v;
}
__device__ __forceinline__ void red2(float* p, float a, float b) {
    atomicAdd(reinterpret_cast<float2*>(p), make_float2(a, b));
}
__device__ __forceinline__ float dot4(float4 a, float4 b) {
    return a.x * b.x + a.y * b.y + a.z * b.z + a.w * b.w;
}
__device__ __forceinline__ float tanhf_fast(float x) {  // x >= 0
    if (x < 1e-4f) return x;
    float e = __expf(2.0f * x);
    return __fdividef(e - 1.0f, e + 1.0f);
}
__device__ __forceinline__ float atanhf_fast(float x) { // 0 <= x <= 1-1e-5
    return 0.5f * __logf(__fdividef(1.0f + x, 1.0f - x));
}

// ---------------- RGAT: 2 edges per warp (16-lane halves, float4) ----------
__global__ void __launch_bounds__(256) k_rgat(
    const float* __restrict__ entP, const float* __restrict__ rel,
    const int* __restrict__ head, const int* __restrict__ tail,
    const int* __restrict__ etype,
    float* __restrict__ sums)
{
    __shared__ float s_rel[NREL * D];
    __shared__ float s_relC[NREL];
    for (int i = threadIdx.x; i < NREL * D; i += blockDim.x) s_rel[i] = rel[i];
    __syncthreads();
    if (threadIdx.x < NREL) {
        float s = 0.0f;
        #pragma unroll 8
        for (int k = 0; k < D; k++) { float v = s_rel[threadIdx.x * D + k]; s += v * v; }
        s_relC[threadIdx.x] = s;
    }
    __syncthreads();

    int lane = threadIdx.x & 31;
    int half = lane >> 4;
    int sl   = lane & 15;
    int e = ((blockIdx.x * blockDim.x + threadIdx.x) >> 5) * 2 + half;  // exact grid

    int h = head[e];
    int t = tail[e];
    int r = etype[e] - 1;

    const float4* e4 = reinterpret_cast<const float4*>(entP);
    float4 he = e4[(size_t)h * 16 + sl];
    float4 te = e4[(size_t)t * 16 + sl];
    float4 re = reinterpret_cast<const float4*>(s_rel)[r * 16 + sl];

    // 5 base reductions (C from smem table)
    float A = hredsum(dot4(he, he));
    float B = hredsum(dot4(te, te));
    float P = hredsum(dot4(he, te));
    float Q = hredsum(dot4(he, re));
    float R = hredsum(dot4(te, re));
    float C = s_relC[r];

    const float MINN = 1e-15f;
    // hh = expmap0(he) = alpha * he
    float nhe   = fmaxf(sqrtf(A), MINN);
    float alpha = __fdividef(tanhf_fast(nhe), nhe);
    float sq    = alpha * alpha * A;
    float omq   = 1.0f - sq;
    float lamden = fmaxf(omq, MINN);
    float lam   = __fdividef(2.0f, lamden);
    // ht = expmap(te, hh) = p1*he + p2*te
    float nte = fmaxf(sqrtf(B), MINN);
    float at  = __fdividef(tanhf_fast(0.5f * lam * nte), nte);
    float y2t = at * at * B;
    float xyt = at * alpha * P;
    float dent = fmaxf(1.0f + 2.0f * xyt + sq * y2t, MINN);
    float p1 = __fdividef((1.0f + 2.0f * xyt + y2t) * alpha, dent);
    float p2 = __fdividef(omq * at, dent);
    // hr = expmap(re, hh) = q1*he + q3*re
    float nre = fmaxf(sqrtf(C), MINN);
    float ar  = __fdividef(tanhf_fast(0.5f * lam * nre), nre);
    float y2r = ar * ar * C;
    float xyr = ar * alpha * Q;
    float denr = fmaxf(1.0f + 2.0f * xyr + sq * y2r, MINN);
    float q1 = __fdividef((1.0f + 2.0f * xyr + y2r) * alpha, denr);
    float q3 = __fdividef(omq * ar, denr);
    // scalar dots
    float sht = p1 * p1 * A + 2.0f * p1 * p2 * P + p2 * p2 * B;
    float shr = q1 * q1 * A + 2.0f * q1 * q3 * Q + q3 * q3 * C;
    float dhh = p1 * q1 * A + p1 * q3 * Q + p2 * q1 * P + p2 * q3 * R;
    // m = mobius_add(ht, hr) = m1*he + m2*te + m3*re
    float denm = fmaxf(1.0f + 2.0f * dhh + sht * shr, MINN);
    float f1 = __fdividef(1.0f + 2.0f * dhh + shr, denm);
    float f2 = __fdividef(1.0f - sht, denm);
    float m1 = f1 * p1 + f2 * q1;
    float m2 = f1 * p2;
    float m3 = f2 * q3;
    float sm = m1 * m1 * A + m2 * m2 * B + m3 * m3 * C
             + 2.0f * (m1 * m2 * P + m1 * m3 * Q + m2 * m3 * R);
    sm = fmaxf(sm, 0.0f);
    // project
    float nm = fmaxf(sqrtf(sm), MINN);
    float scale = (nm > 0.999f) ? __fdividef(0.999f, nm) : 1.0f;
    float sqres = sm * scale * scale;
    // logmap: sub = u1*he + u2*te + u3*re
    float dhres = scale * alpha * (m1 * A + m2 * P + m3 * Q);
    float xy = -dhres;
    float denl = fmaxf(1.0f + 2.0f * xy + sq * sqres, MINN);
    float gg1 = __fdividef(1.0f + 2.0f * xy + sqres, denl);
    float gg2 = __fdividef(omq, denl);
    float u1 = -gg1 * alpha + gg2 * scale * m1;
    float u2 = gg2 * scale * m2;
    float u3 = gg2 * scale * m3;
    float ssub = u1 * u1 * A + u2 * u2 * B + u3 * u3 * C
               + 2.0f * (u1 * u2 * P + u1 * u3 * Q + u2 * u3 * R);
    ssub = fmaxf(ssub, 0.0f);
    float nsub = fmaxf(sqrtf(ssub), MINN);
    float coef = lamden * __fdividef(atanhf_fast(fminf(nsub, 1.0f - 1e-5f)), nsub);
    // ricci coefficient
    float stere = B + 2.0f * R + C;
    float epst = __fdividef(1e-7f, fmaxf(sqrtf(stere), 1e-12f));

    float c1 = coef * u1;
    float c2 = coef * u2 + epst;
    float c3 = coef * u3 + epst;

    float ox = fmaxf(c1 * he.x + c2 * te.x + c3 * re.x, 0.0f);
    float oy = fmaxf(c1 * he.y + c2 * te.y + c3 * re.y, 0.0f);
    float oz = fmaxf(c1 * he.z + c2 * te.z + c3 * re.z, 0.0f);
    float ow = fmaxf(c1 * he.w + c2 * te.w + c3 * re.w, 0.0f);

    float* base = sums + (size_t)h * D + sl * 4;
    red2(base, ox, oy);
    red2(base + 2, oz, ow);
}

// ---------------- l2norm in place (mean folds into norm) -------------------
__global__ void __launch_bounds__(256) k_post(float* __restrict__ buf)
{
    int w = (blockIdx.x * blockDim.x + threadIdx.x) >> 5;
    int lane = threadIdx.x & 31;
    float2* b2 = reinterpret_cast<float2*>(buf);
    float2 v = b2[(size_t)w * 32 + lane];
    float s = wredsum(v.x * v.x + v.y * v.y);
    float inv = __fdividef(1.0f, fmaxf(sqrtf(s), 1e-12f));
    v.x *= inv; v.y *= inv;
    b2[(size_t)w * 32 + lane] = v;
}

// ---------------- embeds = concat(u, 0.25*e0 + 0.5*n1 + n2) ----------------
__global__ void __launch_bounds__(256) k_embeds(
    const float* __restrict__ u, const float* __restrict__ e0,
    const float* __restrict__ n1, const float* __restrict__ n2,
    float* __restrict__ Aout, float* __restrict__ out)
{
    int i = blockIdx.x * blockDim.x + threadIdx.x;  // float2 index, exact grid
    int row = i >> 5;
    float2 v;
    if (row < NUSER) {
        v = reinterpret_cast<const float2*>(u)[i];
    } else {
        int j = i - NUSER * 32;
        float2 a = reinterpret_cast<const float2*>(e0)[j];
        float2 b = reinterpret_cast<const float2*>(n1)[j];
        float2 c = reinterpret_cast<const float2*>(n2)[j];
        v.x = 0.25f * a.x + 0.5f * b.x + c.x;
        v.y = 0.25f * a.y + 0.5f * b.y + c.y;
    }
    reinterpret_cast<float2*>(Aout)[i] = v;
    reinterpret_cast<float2*>(out)[i] = v;
}

// ---------------- adj CSR build --------------------------------------------
__global__ void k_hist(const int* __restrict__ key, int n, int* __restrict__ cnt) {
    int i = blockIdx.x * blockDim.x + threadIdx.x;
    if (i < n) atomicAdd(&cnt[key[i]], 1);
}
__global__ void k_blocksum(const int* __restrict__ cnt, int n, int* __restrict__ bs) {
    __shared__ int sh[1024];
    int i = blockIdx.x * 1024 + threadIdx.x;
    sh[threadIdx.x] = (i < n) ? cnt[i] : 0;
    __syncthreads();
    for (int s = 512; s > 0; s >>= 1) {
        if (threadIdx.x < s) sh[threadIdx.x] += sh[threadIdx.x + s];
        __syncthreads();
    }
    if (threadIdx.x == 0) bs[blockIdx.x] = sh[0];
}
__global__ void k_scanbsums(int* __restrict__ bs, int nb) {
    __shared__ int sh[1024];
    int v = (threadIdx.x < nb) ? bs[threadIdx.x] : 0;
    sh[threadIdx.x] = v;
    __syncthreads();
    for (int off = 1; off < 1024; off <<= 1) {
        int t = (threadIdx.x >= off) ? sh[threadIdx.x - off] : 0;
        __syncthreads();
        sh[threadIdx.x] += t;
        __syncthreads();
    }
    if (threadIdx.x < nb) bs[threadIdx.x] = sh[threadIdx.x] - v;  // exclusive
}
__global__ void k_scanblock(const int* __restrict__ cnt, int n,
                            const int* __restrict__ bs,
                            int* __restrict__ ptr, int* __restrict__ cur) {
    __shared__ int sh[1024];
    int i = blockIdx.x * 1024 + threadIdx.x;
    int v = (i < n) ? cnt[i] : 0;
    sh[threadIdx.x] = v;
    __syncthreads();
    for (int off = 1; off < 1024; off <<= 1) {
        int t = (threadIdx.x >= off) ? sh[threadIdx.x - off] : 0;
        __syncthreads();
        sh[threadIdx.x] += t;
        __syncthreads();
    }
    int excl = sh[threadIdx.x] - v + bs[blockIdx.x];
    if (i < n) { ptr[i] = excl; cur[i] = excl; }
    if (i == n - 1) ptr[n] = excl + v;
}
__global__ void k_ascatter(const int* __restrict__ row, const int* __restrict__ col,
                           const float* __restrict__ val,
                           int* __restrict__ cur,
                           int* __restrict__ ocol, float* __restrict__ oval) {
    int i = blockIdx.x * blockDim.x + threadIdx.x;
    if (i >= NNZ) return;
    int pos = atomicAdd(&cur[row[i]], 1);
    ocol[pos] = col[i];
    oval[pos] = val[i];
}

// ---------------- CSR SpMM: warp per row, uniform loads, fused out += ------
template <int STORE>
__global__ void __launch_bounds__(256) k_spmm(
    const float* __restrict__ curbuf, const int* __restrict__ ptr,
    const int* __restrict__ cols, const float* __restrict__ vals,
    float* __restrict__ nxt, float* __restrict__ out)
{
    int w = (blockIdx.x * blockDim.x + threadIdx.x) >> 5;
    int lane = threadIdx.x & 31;
    int beg = ptr[w], end = ptr[w + 1];
    const float2* cb = reinterpret_cast<const float2*>(curbuf);
    float2 acc = make_float2(0.0f, 0.0f);
    int j = beg;
    for (; j + 8 <= end; j += 8) {
        #pragma unroll
        for (int u = 0; u < 8; u++) {
            int   cc = cols[j + u];
            float vv = vals[j + u];
            float2 x = cb[(size_t)cc * 32 + lane];
            acc.x = fmaf(vv, x.x, acc.x);
            acc.y = fmaf(vv, x.y, acc.y);
        }
    }
    for (; j < end; j++) {
        int cc = cols[j]; float vv = vals[j];
        float2 x = cb[(size_t)cc * 32 + lane];
        acc.x = fmaf(vv, x.x, acc.x);
        acc.y = fmaf(vv, x.y, acc.y);
    }
    size_t o = (size_t)w * 32 + lane;
    if (STORE) reinterpret_cast<float2*>(nxt)[o] = acc;
    float2 ov = reinterpret_cast<float2*>(out)[o];
    ov.x += acc.x; ov.y += acc.y;
    reinterpret_cast<float2*>(out)[o] = ov;
}

// ---------------- launch ---------------------------------------------------
extern "C" void kernel_launch(void* const* d_in, const int* in_sizes, int n_in,
                              void* d_out, int out_size)
{
    const float* uE   = (const float*)d_in[0];
    const float* eE   = (const float*)d_in[1];
    const float* rE   = (const float*)d_in[2];
    const float* aval = (const float*)d_in[3];
    const int*   eh   = (const int*)d_in[4];
    const int*   et   = (const int*)d_in[5];
    const int*   ety  = (const int*)d_in[6];
    const int*   arow = (const int*)d_in[7];
    const int*   acol = (const int*)d_in[8];
    float* out = (float*)d_out;

    float *sA, *sB, *A, *B, *avalS;
    int *acnt, *aptr, *acur, *acolS, *bsums;
    cudaGetSymbolAddress((void**)&sA,    g_sA);
    cudaGetSymbolAddress((void**)&sB,    g_sB);
    cudaGetSymbolAddress((void**)&A,     g_A);
    cudaGetSymbolAddress((void**)&B,     g_B);
    cudaGetSymbolAddress((void**)&acnt,  g_acnt);
    cudaGetSymbolAddress((void**)&aptr,  g_aptr);
    cudaGetSymbolAddress((void**)&acur,  g_acur);
    cudaGetSymbolAddress((void**)&acolS, g_acol);
    cudaGetSymbolAddress((void**)&avalS, g_aval);
    cudaGetSymbolAddress((void**)&bsums, g_bsums);

    const size_t entBytes = (size_t)NENT * D * sizeof(float);
    const int nbA = (NUI + 1023) / 1024;   // 147

    // Launch order chosen so k_rgat is the 5th launch (ncu -s 5 capture).
    cudaMemsetAsync(sA, 0, entBytes);                          // 1
    cudaMemsetAsync(sB, 0, entBytes);                          // 2
    cudaMemsetAsync(acnt, 0, NUI * sizeof(int));               // 3
    k_hist<<<(NNZ + 255) / 256, 256>>>(arow, NNZ, acnt);       // 4

    // ---- RGAT hop 1
    k_rgat<<<NEDGE / 16, 256>>>(eE, rE, eh, et, ety, sA);      // 5 <- profiled
    k_post<<<NENT / 8, 256>>>(sA);                             // 6
    // ---- RGAT hop 2
    k_rgat<<<NEDGE / 16, 256>>>(sA, rE, eh, et, ety, sB);      // 7
    k_post<<<NENT / 8, 256>>>(sB);                             // 8

    // ---- finish adj CSR build
    k_blocksum<<<nbA, 1024>>>(acnt, NUI, bsums);
    k_scanbsums<<<1, 1024>>>(bsums, nbA);
    k_scanblock<<<nbA, 1024>>>(acnt, NUI, bsums, aptr, acur);
    k_ascatter<<<(NNZ + 255) / 256, 256>>>(arow, acol, aval, acur, acolS, avalS);

    // ---- embeds + total init (ent_res = 0.25*e0 + 0.5*n1 + n2)
    k_embeds<<<NUI * 32 / 256, 256>>>(uE, eE, sA, sB, A, out);

    // ---- GCN layers via CSR, out += fused
    k_spmm<1><<<NUI / 8, 256>>>(A, aptr, acolS, avalS, B, out);
    k_spmm<0><<<NUI / 8, 256>>>(B, aptr, acolS, avalS, nullptr, out);
}

// round 6
// speedup vs baseline: 1.5214x; 1.1492x over previous
#include <cuda_runtime.h>
#include <math.h>

#define NUSER 100000
#define NITEM 50000
#define NENT  200000
#define NREL  32
#define D     64
#define NEDGE 500000
#define NNZ   2000000
#define NUI   (NUSER + NITEM)
#define FULL  0xffffffffu

// ---------------- scratch (device globals; no runtime allocation) ----------
__device__ float g_sA[NENT * D];    // hop1 sums -> ent1 (in-place post)
__device__ float g_sB[NENT * D];    // hop2 sums -> ent2
__device__ float g_nrm1[NENT];      // ||eE_i||^2 (hop1 input norms)
__device__ float g_nrm2[NENT];      // hop2 input norms (1 or 0)
__device__ float g_nrmX[NENT];      // dummy sink
__device__ float g_A[NUI * D];      // embeds
__device__ float g_B[NUI * D];      // gcn intermediate
__device__ int   g_acnt[NUI];
__device__ int   g_aptr[NUI + 1];
__device__ int   g_acur[NUI];
__device__ int   g_acol[NNZ];
__device__ float g_aval[NNZ];
__device__ int   g_bsums[1024];

// ---------------- helpers ----------------
__device__ __forceinline__ float wredsum(float v) {
    v += __shfl_xor_sync(FULL, v, 16);
    v += __shfl_xor_sync(FULL, v, 8);
    v += __shfl_xor_sync(FULL, v, 4);
    v += __shfl_xor_sync(FULL, v, 2);
    v += __shfl_xor_sync(FULL, v, 1);
    return v;
}
__device__ __forceinline__ float r8sum(float v) {   // 8-lane groups
    v += __shfl_xor_sync(FULL, v, 4);
    v += __shfl_xor_sync(FULL, v, 2);
    v += __shfl_xor_sync(FULL, v, 1);
    return v;
}
__device__ __forceinline__ float dot4(float4 a, float4 b) {
    return a.x * b.x + a.y * b.y + a.z * b.z + a.w * b.w;
}
__device__ __forceinline__ float tanhf_fast(float x) {  // x >= 0
    if (x < 1e-4f) return x;
    float e = __expf(2.0f * x);
    return __fdividef(e - 1.0f, e + 1.0f);
}
__device__ __forceinline__ float atanhf_fast(float x) { // 0 <= x <= 1-1e-5
    return 0.5f * __logf(__fdividef(1.0f + x, 1.0f - x));
}

// ---------------- per-row squared norms: 4 rows/warp -----------------------
__global__ void __launch_bounds__(256) k_norms(const float* __restrict__ ent,
                                               float* __restrict__ nrm)
{
    int lane = threadIdx.x & 31;
    int g = lane >> 3, sl = lane & 7;
    int row = ((blockIdx.x * blockDim.x + threadIdx.x) >> 5) * 4 + g;  // exact grid
    const float4* e4 = reinterpret_cast<const float4*>(ent);
    float4 a = e4[(size_t)row * 16 + sl * 2];
    float4 b = e4[(size_t)row * 16 + sl * 2 + 1];
    float s = r8sum(dot4(a, a) + dot4(b, b));
    if (sl == 0) nrm[row] = s;
}

// ---------------- RGAT: 4 edges per warp (8-lane groups) -------------------
__global__ void __launch_bounds__(256) k_rgat(
    const float* __restrict__ entP, const float* __restrict__ rel,
    const int* __restrict__ head, const int* __restrict__ tail,
    const int* __restrict__ etype, const float* __restrict__ nrm,
    float* __restrict__ sums)
{
    __shared__ float s_rel[NREL * D];
    __shared__ float s_relC[NREL];
    for (int i = threadIdx.x; i < NREL * D; i += blockDim.x) s_rel[i] = rel[i];
    __syncthreads();
    if (threadIdx.x < NREL) {
        float s = 0.0f;
        #pragma unroll 8
        for (int k = 0; k < D; k++) { float v = s_rel[threadIdx.x * D + k]; s += v * v; }
        s_relC[threadIdx.x] = s;
    }
    __syncthreads();

    int lane = threadIdx.x & 31;
    int g  = lane >> 3;
    int sl = lane & 7;
    int e = ((blockIdx.x * blockDim.x + threadIdx.x) >> 5) * 4 + g;  // exact grid

    int h = head[e];
    int t = tail[e];
    int r = etype[e] - 1;

    const float4* e4 = reinterpret_cast<const float4*>(entP);
    const float4* r4 = reinterpret_cast<const float4*>(s_rel);
    float4 he0 = e4[(size_t)h * 16 + sl * 2];
    float4 he1 = e4[(size_t)h * 16 + sl * 2 + 1];
    float4 te0 = e4[(size_t)t * 16 + sl * 2];
    float4 te1 = e4[(size_t)t * 16 + sl * 2 + 1];
    float4 re0 = r4[r * 16 + sl * 2];
    float4 re1 = r4[r * 16 + sl * 2 + 1];

    // 3 reductions (A,B from norm array, C from smem table)
    float A = nrm[h];
    float B = nrm[t];
    float C = s_relC[r];
    float P = r8sum(dot4(he0, te0) + dot4(he1, te1));
    float Q = r8sum(dot4(he0, re0) + dot4(he1, re1));
    float R = r8sum(dot4(te0, re0) + dot4(te1, re1));

    const float MINN = 1e-15f;
    // hh = expmap0(he) = alpha * he
    float nhe   = fmaxf(sqrtf(A), MINN);
    float alpha = __fdividef(tanhf_fast(nhe), nhe);
    float sq    = alpha * alpha * A;
    float omq   = 1.0f - sq;
    float lamden = fmaxf(omq, MINN);
    float lam   = __fdividef(2.0f, lamden);
    // ht = expmap(te, hh) = p1*he + p2*te
    float nte = fmaxf(sqrtf(B), MINN);
    float at  = __fdividef(tanhf_fast(0.5f * lam * nte), nte);
    float y2t = at * at * B;
    float xyt = at * alpha * P;
    float dent = fmaxf(1.0f + 2.0f * xyt + sq * y2t, MINN);
    float p1 = __fdividef((1.0f + 2.0f * xyt + y2t) * alpha, dent);
    float p2 = __fdividef(omq * at, dent);
    // hr = expmap(re, hh) = q1*he + q3*re
    float nre = fmaxf(sqrtf(C), MINN);
    float ar  = __fdividef(tanhf_fast(0.5f * lam * nre), nre);
    float y2r = ar * ar * C;
    float xyr = ar * alpha * Q;
    float denr = fmaxf(1.0f + 2.0f * xyr + sq * y2r, MINN);
    float q1 = __fdividef((1.0f + 2.0f * xyr + y2r) * alpha, denr);
    float q3 = __fdividef(omq * ar, denr);
    // scalar dots
    float sht = p1 * p1 * A + 2.0f * p1 * p2 * P + p2 * p2 * B;
    float shr = q1 * q1 * A + 2.0f * q1 * q3 * Q + q3 * q3 * C;
    float dhh = p1 * q1 * A + p1 * q3 * Q + p2 * q1 * P + p2 * q3 * R;
    // m = mobius_add(ht, hr) = m1*he + m2*te + m3*re
    float denm = fmaxf(1.0f + 2.0f * dhh + sht * shr, MINN);
    float f1 = __fdividef(1.0f + 2.0f * dhh + shr, denm);
    float f2 = __fdividef(1.0f - sht, denm);
    float m1 = f1 * p1 + f2 * q1;
    float m2 = f1 * p2;
    float m3 = f2 * q3;
    float sm = m1 * m1 * A + m2 * m2 * B + m3 * m3 * C
             + 2.0f * (m1 * m2 * P + m1 * m3 * Q + m2 * m3 * R);
    sm = fmaxf(sm, 0.0f);
    // project
    float nm = fmaxf(sqrtf(sm), MINN);
    float scale = (nm > 0.999f) ? __fdividef(0.999f, nm) : 1.0f;
    float sqres = sm * scale * scale;
    // logmap: sub = u1*he + u2*te + u3*re
    float dhres = scale * alpha * (m1 * A + m2 * P + m3 * Q);
    float xy = -dhres;
    float denl = fmaxf(1.0f + 2.0f * xy + sq * sqres, MINN);
    float gg1 = __fdividef(1.0f + 2.0f * xy + sqres, denl);
    float gg2 = __fdividef(omq, denl);
    float u1 = -gg1 * alpha + gg2 * scale * m1;
    float u2 = gg2 * scale * m2;
    float u3 = gg2 * scale * m3;
    float ssub = u1 * u1 * A + u2 * u2 * B + u3 * u3 * C
               + 2.0f * (u1 * u2 * P + u1 * u3 * Q + u2 * u3 * R);
    ssub = fmaxf(ssub, 0.0f);
    float nsub = fmaxf(sqrtf(ssub), MINN);
    float coef = lamden * __fdividef(atanhf_fast(fminf(nsub, 1.0f - 1e-5f)), nsub);
    // ricci coefficient
    float stere = B + 2.0f * R + C;
    float epst = __fdividef(1e-7f, fmaxf(sqrtf(stere), 1e-12f));

    float c1 = coef * u1;
    float c2 = coef * u2 + epst;
    float c3 = coef * u3 + epst;

    float4 o0, o1;
    o0.x = fmaxf(c1 * he0.x + c2 * te0.x + c3 * re0.x, 0.0f);
    o0.y = fmaxf(c1 * he0.y + c2 * te0.y + c3 * re0.y, 0.0f);
    o0.z = fmaxf(c1 * he0.z + c2 * te0.z + c3 * re0.z, 0.0f);
    o0.w = fmaxf(c1 * he0.w + c2 * te0.w + c3 * re0.w, 0.0f);
    o1.x = fmaxf(c1 * he1.x + c2 * te1.x + c3 * re1.x, 0.0f);
    o1.y = fmaxf(c1 * he1.y + c2 * te1.y + c3 * re1.y, 0.0f);
    o1.z = fmaxf(c1 * he1.z + c2 * te1.z + c3 * re1.z, 0.0f);
    o1.w = fmaxf(c1 * he1.w + c2 * te1.w + c3 * re1.w, 0.0f);

    float4* base = reinterpret_cast<float4*>(sums + (size_t)h * D + sl * 8);
    atomicAdd(base, o0);
    atomicAdd(base + 1, o1);
}

// ---------------- l2norm in place (mean folds into norm) + next norms ------
__global__ void __launch_bounds__(256) k_post(float* __restrict__ buf,
                                              float* __restrict__ nrmOut)
{
    int w = (blockIdx.x * blockDim.x + threadIdx.x) >> 5;
    int lane = threadIdx.x & 31;
    float2* b2 = reinterpret_cast<float2*>(buf);
    float2 v = b2[(size_t)w * 32 + lane];
    float s = wredsum(v.x * v.x + v.y * v.y);
    float inv = __fdividef(1.0f, fmaxf(sqrtf(s), 1e-12f));
    v.x *= inv; v.y *= inv;
    b2[(size_t)w * 32 + lane] = v;
    if (lane == 0) nrmOut[w] = (s > 0.0f) ? 1.0f : 0.0f;
}

// ---------------- embeds = concat(u, 0.25*e0 + 0.5*n1 + n2) ----------------
__global__ void __launch_bounds__(256) k_embeds(
    const float* __restrict__ u, const float* __restrict__ e0,
    const float* __restrict__ n1, const float* __restrict__ n2,
    float* __restrict__ Aout, float* __restrict__ out)
{
    int i = blockIdx.x * blockDim.x + threadIdx.x;  // float2 index, exact grid
    int row = i >> 5;
    float2 v;
    if (row < NUSER) {
        v = reinterpret_cast<const float2*>(u)[i];
    } else {
        int j = i - NUSER * 32;
        float2 a = reinterpret_cast<const float2*>(e0)[j];
        float2 b = reinterpret_cast<const float2*>(n1)[j];
        float2 c = reinterpret_cast<const float2*>(n2)[j];
        v.x = 0.25f * a.x + 0.5f * b.x + c.x;
        v.y = 0.25f * a.y + 0.5f * b.y + c.y;
    }
    reinterpret_cast<float2*>(Aout)[i] = v;
    reinterpret_cast<float2*>(out)[i] = v;
}

// ---------------- adj CSR build --------------------------------------------
__global__ void k_hist(const int* __restrict__ key, int n, int* __restrict__ cnt) {
    int i = blockIdx.x * blockDim.x + threadIdx.x;
    if (i < n) atomicAdd(&cnt[key[i]], 1);
}
__global__ void k_blocksum(const int* __restrict__ cnt, int n, int* __restrict__ bs) {
    __shared__ int sh[1024];
    int i = blockIdx.x * 1024 + threadIdx.x;
    sh[threadIdx.x] = (i < n) ? cnt[i] : 0;
    __syncthreads();
    for (int s = 512; s > 0; s >>= 1) {
        if (threadIdx.x < s) sh[threadIdx.x] += sh[threadIdx.x + s];
        __syncthreads();
    }
    if (threadIdx.x == 0) bs[blockIdx.x] = sh[0];
}
__global__ void k_scanbsums(int* __restrict__ bs, int nb) {
    __shared__ int sh[1024];
    int v = (threadIdx.x < nb) ? bs[threadIdx.x] : 0;
    sh[threadIdx.x] = v;
    __syncthreads();
    for (int off = 1; off < 1024; off <<= 1) {
        int t = (threadIdx.x >= off) ? sh[threadIdx.x - off] : 0;
        __syncthreads();
        sh[threadIdx.x] += t;
        __syncthreads();
    }
    if (threadIdx.x < nb) bs[threadIdx.x] = sh[threadIdx.x] - v;  // exclusive
}
__global__ void k_scanblock(const int* __restrict__ cnt, int n,
                            const int* __restrict__ bs,
                            int* __restrict__ ptr, int* __restrict__ cur) {
    __shared__ int sh[1024];
    int i = blockIdx.x * 1024 + threadIdx.x;
    int v = (i < n) ? cnt[i] : 0;
    sh[threadIdx.x] = v;
    __syncthreads();
    for (int off = 1; off < 1024; off <<= 1) {
        int t = (threadIdx.x >= off) ? sh[threadIdx.x - off] : 0;
        __syncthreads();
        sh[threadIdx.x] += t;
        __syncthreads();
    }
    int excl = sh[threadIdx.x] - v + bs[blockIdx.x];
    if (i < n) { ptr[i] = excl; cur[i] = excl; }
    if (i == n - 1) ptr[n] = excl + v;
}
__global__ void k_ascatter(const int* __restrict__ row, const int* __restrict__ col,
                           const float* __restrict__ val,
                           int* __restrict__ cur,
                           int* __restrict__ ocol, float* __restrict__ oval) {
    int i = blockIdx.x * blockDim.x + threadIdx.x;
    if (i >= NNZ) return;
    int pos = atomicAdd(&cur[row[i]], 1);
    ocol[pos] = col[i];
    oval[pos] = val[i];
}

// ---------------- CSR SpMM: warp per row, uniform loads, fused out += ------
template <int STORE>
__global__ void __launch_bounds__(256) k_spmm(
    const float* __restrict__ curbuf, const int* __restrict__ ptr,
    const int* __restrict__ cols, const float* __restrict__ vals,
    float* __restrict__ nxt, float* __restrict__ out)
{
    int w = (blockIdx.x * blockDim.x + threadIdx.x) >> 5;
    int lane = threadIdx.x & 31;
    int beg = ptr[w], end = ptr[w + 1];
    const float2* cb = reinterpret_cast<const float2*>(curbuf);
    float2 acc = make_float2(0.0f, 0.0f);
    int j = beg;
    for (; j + 8 <= end; j += 8) {
        #pragma unroll
        for (int u = 0; u < 8; u++) {
            int   cc = cols[j + u];
            float vv = vals[j + u];
            float2 x = cb[(size_t)cc * 32 + lane];
            acc.x = fmaf(vv, x.x, acc.x);
            acc.y = fmaf(vv, x.y, acc.y);
        }
    }
    for (; j < end; j++) {
        int cc = cols[j]; float vv = vals[j];
        float2 x = cb[(size_t)cc * 32 + lane];
        acc.x = fmaf(vv, x.x, acc.x);
        acc.y = fmaf(vv, x.y, acc.y);
    }
    size_t o = (size_t)w * 32 + lane;
    if (STORE) reinterpret_cast<float2*>(nxt)[o] = acc;
    float2 ov = reinterpret_cast<float2*>(out)[o];
    ov.x += acc.x; ov.y += acc.y;
    reinterpret_cast<float2*>(out)[o] = ov;
}

// ---------------- launch ---------------------------------------------------
extern "C" void kernel_launch(void* const* d_in, const int* in_sizes, int n_in,
                              void* d_out, int out_size)
{
    const float* uE   = (const float*)d_in[0];
    const float* eE   = (const float*)d_in[1];
    const float* rE   = (const float*)d_in[2];
    const float* aval = (const float*)d_in[3];
    const int*   eh   = (const int*)d_in[4];
    const int*   et   = (const int*)d_in[5];
    const int*   ety  = (const int*)d_in[6];
    const int*   arow = (const int*)d_in[7];
    const int*   acol = (const int*)d_in[8];
    float* out = (float*)d_out;

    float *sA, *sB, *nrm1, *nrm2, *nrmX, *A, *B, *avalS;
    int *acnt, *aptr, *acur, *acolS, *bsums;
    cudaGetSymbolAddress((void**)&sA,    g_sA);
    cudaGetSymbolAddress((void**)&sB,    g_sB);
    cudaGetSymbolAddress((void**)&nrm1,  g_nrm1);
    cudaGetSymbolAddress((void**)&nrm2,  g_nrm2);
    cudaGetSymbolAddress((void**)&nrmX,  g_nrmX);
    cudaGetSymbolAddress((void**)&A,     g_A);
    cudaGetSymbolAddress((void**)&B,     g_B);
    cudaGetSymbolAddress((void**)&acnt,  g_acnt);
    cudaGetSymbolAddress((void**)&aptr,  g_aptr);
    cudaGetSymbolAddress((void**)&acur,  g_acur);
    cudaGetSymbolAddress((void**)&acolS, g_acol);
    cudaGetSymbolAddress((void**)&avalS, g_aval);
    cudaGetSymbolAddress((void**)&bsums, g_bsums);

    const size_t entBytes = (size_t)NENT * D * sizeof(float);
    const int nbA = (NUI + 1023) / 1024;   // 147

    // Launch order chosen so k_rgat is the 5th launch (ncu -s 5 capture).
    cudaMemsetAsync(sA, 0, entBytes);                          // 1
    cudaMemsetAsync(sB, 0, entBytes);                          // 2
    cudaMemsetAsync(acnt, 0, NUI * sizeof(int));               // 3
    k_norms<<<NENT / 32, 256>>>(eE, nrm1);                     // 4

    // ---- RGAT hop 1
    k_rgat<<<NEDGE / 32, 256>>>(eE, rE, eh, et, ety, nrm1, sA);   // 5 <- profiled
    k_post<<<NENT / 8, 256>>>(sA, nrm2);                          // 6
    // ---- RGAT hop 2
    k_rgat<<<NEDGE / 32, 256>>>(sA, rE, eh, et, ety, nrm2, sB);   // 7
    k_post<<<NENT / 8, 256>>>(sB, nrmX);                          // 8

    // ---- adj CSR build
    k_hist<<<(NNZ + 255) / 256, 256>>>(arow, NNZ, acnt);
    k_blocksum<<<nbA, 1024>>>(acnt, NUI, bsums);
    k_scanbsums<<<1, 1024>>>(bsums, nbA);
    k_scanblock<<<nbA, 1024>>>(acnt, NUI, bsums, aptr, acur);
    k_ascatter<<<(NNZ + 255) / 256, 256>>>(arow, acol, aval, acur, acolS, avalS);

    // ---- embeds + total init (ent_res = 0.25*e0 + 0.5*n1 + n2)
    k_embeds<<<NUI * 32 / 256, 256>>>(uE, eE, sA, sB, A, out);

    // ---- GCN layers via CSR, out += fused
    k_spmm<1><<<NUI / 8, 256>>>(A, aptr, acolS, avalS, B, out);
    k_spmm<0><<<NUI / 8, 256>>>(B, aptr, acolS, avalS, nullptr, out);
}

// round 7
// speedup vs baseline: 1.7098x; 1.1238x over previous
#include <cuda_runtime.h>
#include <math.h>

#define NUSER 100000
#define NITEM 50000
#define NENT  200000
#define NREL  32
#define D     64
#define NEDGE 500000
#define NNZ   2000000
#define NUI   (NUSER + NITEM)
#define FULL  0xffffffffu

// ---------------- scratch (device globals; no runtime allocation) ----------
__device__ float g_sA[NENT * D];     // hop1 sums (raw, unnormalized)
__device__ float g_sB[NITEM * D];    // hop2 sums (only item rows needed)
__device__ float g_nrm1[NENT];       // ||eE_i||^2
__device__ float g_invn[NENT];       // 1/||sA_i|| (0 if zero row)
__device__ float g_A[NUI * D];       // embeds
__device__ float g_B[NUI * D];       // gcn intermediate
// filtered edges for hop 2 (head < NITEM)
__device__ int   g_fh [NEDGE];
__device__ int   g_ft [NEDGE];
__device__ int   g_fr [NEDGE];
__device__ int   g_fcnt[1];
// adj CSR
__device__ int   g_acnt[NUI];
__device__ int   g_aptr[NUI + 1];
__device__ int   g_acur[NUI];
__device__ int   g_acol[NNZ];
__device__ float g_aval[NNZ];
__device__ int   g_bsums[1024];

// ---------------- helpers ----------------
__device__ __forceinline__ float wredsum(float v) {
    v += __shfl_xor_sync(FULL, v, 16);
    v += __shfl_xor_sync(FULL, v, 8);
    v += __shfl_xor_sync(FULL, v, 4);
    v += __shfl_xor_sync(FULL, v, 2);
    v += __shfl_xor_sync(FULL, v, 1);
    return v;
}
__device__ __forceinline__ float r8sum(float v) {   // 8-lane groups
    v += __shfl_xor_sync(FULL, v, 4);
    v += __shfl_xor_sync(FULL, v, 2);
    v += __shfl_xor_sync(FULL, v, 1);
    return v;
}
__device__ __forceinline__ float dot4(float4 a, float4 b) {
    return a.x * b.x + a.y * b.y + a.z * b.z + a.w * b.w;
}
__device__ __forceinline__ float tanhf_fast(float x) {  // x >= 0
    if (x < 1e-4f) return x;
    float e = __expf(2.0f * x);
    return __fdividef(e - 1.0f, e + 1.0f);
}
__device__ __forceinline__ float atanhf_fast(float x) { // 0 <= x <= 1-1e-5
    return 0.5f * __logf(__fdividef(1.0f + x, 1.0f - x));
}

// ---------------- per-row squared norms: 4 rows/warp -----------------------
__global__ void __launch_bounds__(256) k_norms(const float* __restrict__ ent,
                                               float* __restrict__ nrm)
{
    int lane = threadIdx.x & 31;
    int g = lane >> 3, sl = lane & 7;
    int row = ((blockIdx.x * blockDim.x + threadIdx.x) >> 5) * 4 + g;  // exact grid
    const float4* e4 = reinterpret_cast<const float4*>(ent);
    float4 a = e4[(size_t)row * 16 + sl * 2];
    float4 b = e4[(size_t)row * 16 + sl * 2 + 1];
    float s = r8sum(dot4(a, a) + dot4(b, b));
    if (sl == 0) nrm[row] = s;
}

// ---------------- inverse norms of sA (no buffer rewrite) ------------------
__global__ void __launch_bounds__(256) k_invn(const float* __restrict__ buf,
                                              float* __restrict__ invn)
{
    int w = (blockIdx.x * blockDim.x + threadIdx.x) >> 5;
    int lane = threadIdx.x & 31;
    const float2* b2 = reinterpret_cast<const float2*>(buf);
    float2 v = b2[(size_t)w * 32 + lane];
    float s = wredsum(v.x * v.x + v.y * v.y);
    if (lane == 0)
        invn[w] = (s > 0.0f) ? __fdividef(1.0f, fmaxf(sqrtf(s), 1e-12f)) : 0.0f;
}

// ---------------- filter edges with head < NITEM for hop 2 -----------------
__global__ void k_filter(const int* __restrict__ head, const int* __restrict__ tail,
                         const int* __restrict__ etype, int* __restrict__ cnt,
                         int* __restrict__ fh, int* __restrict__ ft, int* __restrict__ fr)
{
    int i = blockIdx.x * blockDim.x + threadIdx.x;
    if (i >= NEDGE) return;
    int h = head[i];
    if (h >= NITEM) return;
    int p = atomicAdd(cnt, 1);
    fh[p] = h;
    ft[p] = tail[i];
    fr[p] = etype[i] - 1;
}

// ---------------- RGAT: 4 edges per warp (8-lane groups) -------------------
// HOP==1: sc = raw squared norms of input rows (input already "normalized" form)
// HOP==2: sc = 1/||row||; input rows are raw; normalization folded into scalars
template <int HOP>
__global__ void __launch_bounds__(256) k_rgat(
    const float* __restrict__ entP, const float* __restrict__ rel,
    const int* __restrict__ head, const int* __restrict__ tail,
    const int* __restrict__ etype, const float* __restrict__ sc,
    const int* __restrict__ nlim,
    float* __restrict__ sums)
{
    __shared__ float s_rel[NREL * D];
    __shared__ float s_relC[NREL];
    for (int i = threadIdx.x; i < NREL * D; i += blockDim.x) s_rel[i] = rel[i];
    __syncthreads();
    if (threadIdx.x < NREL) {
        float s = 0.0f;
        #pragma unroll 8
        for (int k = 0; k < D; k++) { float v = s_rel[threadIdx.x * D + k]; s += v * v; }
        s_relC[threadIdx.x] = s;
    }
    __syncthreads();

    int lane = threadIdx.x & 31;
    int g  = lane >> 3;
    int sl = lane & 7;
    int e = ((blockIdx.x * blockDim.x + threadIdx.x) >> 5) * 4 + g;

    if (HOP == 2) { if (e >= *nlim) return; }

    int h = head[e];
    int t = tail[e];
    int r = (HOP == 1) ? (etype[e] - 1) : etype[e];

    const float4* e4 = reinterpret_cast<const float4*>(entP);
    const float4* r4 = reinterpret_cast<const float4*>(s_rel);
    float4 he0 = e4[(size_t)h * 16 + sl * 2];
    float4 he1 = e4[(size_t)h * 16 + sl * 2 + 1];
    float4 te0 = e4[(size_t)t * 16 + sl * 2];
    float4 te1 = e4[(size_t)t * 16 + sl * 2 + 1];
    float4 re0 = r4[r * 16 + sl * 2];
    float4 re1 = r4[r * 16 + sl * 2 + 1];

    float A, B, ih = 1.0f, it = 1.0f;
    if (HOP == 1) {
        A = sc[h];
        B = sc[t];
    } else {
        ih = sc[h]; it = sc[t];
        A = (ih > 0.0f) ? 1.0f : 0.0f;
        B = (it > 0.0f) ? 1.0f : 0.0f;
    }
    float C = s_relC[r];
    float P = r8sum(dot4(he0, te0) + dot4(he1, te1));
    float Q = r8sum(dot4(he0, re0) + dot4(he1, re1));
    float R = r8sum(dot4(te0, re0) + dot4(te1, re1));
    if (HOP == 2) { P *= ih * it; Q *= ih; R *= it; }

    const float MINN = 1e-15f;
    // hh = expmap0(he) = alpha * he
    float nhe   = fmaxf(sqrtf(A), MINN);
    float alpha = __fdividef(tanhf_fast(nhe), nhe);
    float sq    = alpha * alpha * A;
    float omq   = 1.0f - sq;
    float lamden = fmaxf(omq, MINN);
    float lam   = __fdividef(2.0f, lamden);
    // ht = expmap(te, hh) = p1*he + p2*te
    float nte = fmaxf(sqrtf(B), MINN);
    float at  = __fdividef(tanhf_fast(0.5f * lam * nte), nte);
    float y2t = at * at * B;
    float xyt = at * alpha * P;
    float dent = fmaxf(1.0f + 2.0f * xyt + sq * y2t, MINN);
    float p1 = __fdividef((1.0f + 2.0f * xyt + y2t) * alpha, dent);
    float p2 = __fdividef(omq * at, dent);
    // hr = expmap(re, hh) = q1*he + q3*re
    float nre = fmaxf(sqrtf(C), MINN);
    float ar  = __fdividef(tanhf_fast(0.5f * lam * nre), nre);
    float y2r = ar * ar * C;
    float xyr = ar * alpha * Q;
    float denr = fmaxf(1.0f + 2.0f * xyr + sq * y2r, MINN);
    float q1 = __fdividef((1.0f + 2.0f * xyr + y2r) * alpha, denr);
    float q3 = __fdividef(omq * ar, denr);
    // scalar dots
    float sht = p1 * p1 * A + 2.0f * p1 * p2 * P + p2 * p2 * B;
    float shr = q1 * q1 * A + 2.0f * q1 * q3 * Q + q3 * q3 * C;
    float dhh = p1 * q1 * A + p1 * q3 * Q + p2 * q1 * P + p2 * q3 * R;
    // m = mobius_add(ht, hr) = m1*he + m2*te + m3*re
    float denm = fmaxf(1.0f + 2.0f * dhh + sht * shr, MINN);
    float f1 = __fdividef(1.0f + 2.0f * dhh + shr, denm);
    float f2 = __fdividef(1.0f - sht, denm);
    float m1 = f1 * p1 + f2 * q1;
    float m2 = f1 * p2;
    float m3 = f2 * q3;
    float sm = m1 * m1 * A + m2 * m2 * B + m3 * m3 * C
             + 2.0f * (m1 * m2 * P + m1 * m3 * Q + m2 * m3 * R);
    sm = fmaxf(sm, 0.0f);
    // project
    float nm = fmaxf(sqrtf(sm), MINN);
    float scale = (nm > 0.999f) ? __fdividef(0.999f, nm) : 1.0f;
    float sqres = sm * scale * scale;
    // logmap: sub = u1*he + u2*te + u3*re
    float dhres = scale * alpha * (m1 * A + m2 * P + m3 * Q);
    float xy = -dhres;
    float denl = fmaxf(1.0f + 2.0f * xy + sq * sqres, MINN);
    float gg1 = __fdividef(1.0f + 2.0f * xy + sqres, denl);
    float gg2 = __fdividef(omq, denl);
    float u1 = -gg1 * alpha + gg2 * scale * m1;
    float u2 = gg2 * scale * m2;
    float u3 = gg2 * scale * m3;
    float ssub = u1 * u1 * A + u2 * u2 * B + u3 * u3 * C
               + 2.0f * (u1 * u2 * P + u1 * u3 * Q + u2 * u3 * R);
    ssub = fmaxf(ssub, 0.0f);
    float nsub = fmaxf(sqrtf(ssub), MINN);
    float coef = lamden * __fdividef(atanhf_fast(fminf(nsub, 1.0f - 1e-5f)), nsub);
    // ricci coefficient (uses normalized te)
    float stere = B + 2.0f * R + C;
    float epst = __fdividef(1e-7f, fmaxf(sqrtf(stere), 1e-12f));

    float c1 = coef * u1;
    float c2 = coef * u2 + epst;
    float c3 = coef * u3 + epst;
    if (HOP == 2) { c1 *= ih; c2 *= it; }   // fold normalization into coefficients

    float4 o0, o1;
    o0.x = fmaxf(c1 * he0.x + c2 * te0.x + c3 * re0.x, 0.0f);
    o0.y = fmaxf(c1 * he0.y + c2 * te0.y + c3 * re0.y, 0.0f);
    o0.z = fmaxf(c1 * he0.z + c2 * te0.z + c3 * re0.z, 0.0f);
    o0.w = fmaxf(c1 * he0.w + c2 * te0.w + c3 * re0.w, 0.0f);
    o1.x = fmaxf(c1 * he1.x + c2 * te1.x + c3 * re1.x, 0.0f);
    o1.y = fmaxf(c1 * he1.y + c2 * te1.y + c3 * re1.y, 0.0f);
    o1.z = fmaxf(c1 * he1.z + c2 * te1.z + c3 * re1.z, 0.0f);
    o1.w = fmaxf(c1 * he1.w + c2 * te1.w + c3 * re1.w, 0.0f);

    float4* base = reinterpret_cast<float4*>(sums + (size_t)h * D + sl * 8);
    atomicAdd(base, o0);
    atomicAdd(base + 1, o1);
}

// ---------------- embeds: warp per row; fuses sB l2norm + residual ---------
__global__ void __launch_bounds__(256) k_embeds(
    const float* __restrict__ u, const float* __restrict__ e0,
    const float* __restrict__ sA, const float* __restrict__ invnA,
    const float* __restrict__ sB,
    float* __restrict__ Aout, float* __restrict__ out)
{
    int w = (blockIdx.x * blockDim.x + threadIdx.x) >> 5;   // row, exact grid
    int lane = threadIdx.x & 31;
    size_t o = (size_t)w * 32 + lane;
    float2 v;
    if (w < NUSER) {
        v = reinterpret_cast<const float2*>(u)[o];
    } else {
        int j = w - NUSER;
        size_t jo = (size_t)j * 32 + lane;
        float2 a = reinterpret_cast<const float2*>(e0)[jo];
        float2 b = reinterpret_cast<const float2*>(sA)[jo];
        float2 c = reinterpret_cast<const float2*>(sB)[jo];
        float ia = invnA[j];
        float s = wredsum(c.x * c.x + c.y * c.y);
        float ic = __fdividef(1.0f, fmaxf(sqrtf(s), 1e-12f));
        v.x = 0.25f * a.x + 0.5f * ia * b.x + ic * c.x;
        v.y = 0.25f * a.y + 0.5f * ia * b.y + ic * c.y;
    }
    reinterpret_cast<float2*>(Aout)[o] = v;
    reinterpret_cast<float2*>(out)[o] = v;
}

// ---------------- adj CSR build --------------------------------------------
__global__ void k_hist(const int* __restrict__ key, int n, int* __restrict__ cnt) {
    int i = blockIdx.x * blockDim.x + threadIdx.x;
    if (i < n) atomicAdd(&cnt[key[i]], 1);
}
__global__ void k_blocksum(const int* __restrict__ cnt, int n, int* __restrict__ bs) {
    __shared__ int sh[1024];
    int i = blockIdx.x * 1024 + threadIdx.x;
    sh[threadIdx.x] = (i < n) ? cnt[i] : 0;
    __syncthreads();
    for (int s = 512; s > 0; s >>= 1) {
        if (threadIdx.x < s) sh[threadIdx.x] += sh[threadIdx.x + s];
        __syncthreads();
    }
    if (threadIdx.x == 0) bs[blockIdx.x] = sh[0];
}
__global__ void k_scanbsums(int* __restrict__ bs, int nb) {
    __shared__ int sh[1024];
    int v = (threadIdx.x < nb) ? bs[threadIdx.x] : 0;
    sh[threadIdx.x] = v;
    __syncthreads();
    for (int off = 1; off < 1024; off <<= 1) {
        int t = (threadIdx.x >= off) ? sh[threadIdx.x - off] : 0;
        __syncthreads();
        sh[threadIdx.x] += t;
        __syncthreads();
    }
    if (threadIdx.x < nb) bs[threadIdx.x] = sh[threadIdx.x] - v;  // exclusive
}
__global__ void k_scanblock(const int* __restrict__ cnt, int n,
                            const int* __restrict__ bs,
                            int* __restrict__ ptr, int* __restrict__ cur) {
    __shared__ int sh[1024];
    int i = blockIdx.x * 1024 + threadIdx.x;
    int v = (i < n) ? cnt[i] : 0;
    sh[threadIdx.x] = v;
    __syncthreads();
    for (int off = 1; off < 1024; off <<= 1) {
        int t = (threadIdx.x >= off) ? sh[threadIdx.x - off] : 0;
        __syncthreads();
        sh[threadIdx.x] += t;
        __syncthreads();
    }
    int excl = sh[threadIdx.x] - v + bs[blockIdx.x];
    if (i < n) { ptr[i] = excl; cur[i] = excl; }
    if (i == n - 1) ptr[n] = excl + v;
}
__global__ void k_ascatter(const int* __restrict__ row, const int* __restrict__ col,
                           const float* __restrict__ val,
                           int* __restrict__ cur,
                           int* __restrict__ ocol, float* __restrict__ oval) {
    int i = blockIdx.x * blockDim.x + threadIdx.x;
    if (i >= NNZ) return;
    int pos = atomicAdd(&cur[row[i]], 1);
    ocol[pos] = col[i];
    oval[pos] = val[i];
}

// ---------------- CSR SpMM: warp per row, uniform loads, fused out += ------
template <int STORE>
__global__ void __launch_bounds__(256) k_spmm(
    const float* __restrict__ curbuf, const int* __restrict__ ptr,
    const int* __restrict__ cols, const float* __restrict__ vals,
    float* __restrict__ nxt, float* __restrict__ out)
{
    int w = (blockIdx.x * blockDim.x + threadIdx.x) >> 5;
    int lane = threadIdx.x & 31;
    int beg = ptr[w], end = ptr[w + 1];
    const float2* cb = reinterpret_cast<const float2*>(curbuf);
    float2 acc = make_float2(0.0f, 0.0f);
    int j = beg;
    for (; j + 8 <= end; j += 8) {
        #pragma unroll
        for (int u = 0; u < 8; u++) {
            int   cc = cols[j + u];
            float vv = vals[j + u];
            float2 x = cb[(size_t)cc * 32 + lane];
            acc.x = fmaf(vv, x.x, acc.x);
            acc.y = fmaf(vv, x.y, acc.y);
        }
    }
    for (; j < end; j++) {
        int cc = cols[j]; float vv = vals[j];
        float2 x = cb[(size_t)cc * 32 + lane];
        acc.x = fmaf(vv, x.x, acc.x);
        acc.y = fmaf(vv, x.y, acc.y);
    }
    size_t o = (size_t)w * 32 + lane;
    if (STORE) reinterpret_cast<float2*>(nxt)[o] = acc;
    float2 ov = reinterpret_cast<float2*>(out)[o];
    ov.x += acc.x; ov.y += acc.y;
    reinterpret_cast<float2*>(out)[o] = ov;
}

// ---------------- launch ---------------------------------------------------
extern "C" void kernel_launch(void* const* d_in, const int* in_sizes, int n_in,
                              void* d_out, int out_size)
{
    const float* uE   = (const float*)d_in[0];
    const float* eE   = (const float*)d_in[1];
    const float* rE   = (const float*)d_in[2];
    const float* aval = (const float*)d_in[3];
    const int*   eh   = (const int*)d_in[4];
    const int*   et   = (const int*)d_in[5];
    const int*   ety  = (const int*)d_in[6];
    const int*   arow = (const int*)d_in[7];
    const int*   acol = (const int*)d_in[8];
    float* out = (float*)d_out;

    float *sA, *sB, *nrm1, *invn, *A, *B, *avalS;
    int *fh, *ft, *fr, *fcnt;
    int *acnt, *aptr, *acur, *acolS, *bsums;
    cudaGetSymbolAddress((void**)&sA,    g_sA);
    cudaGetSymbolAddress((void**)&sB,    g_sB);
    cudaGetSymbolAddress((void**)&nrm1,  g_nrm1);
    cudaGetSymbolAddress((void**)&invn,  g_invn);
    cudaGetSymbolAddress((void**)&A,     g_A);
    cudaGetSymbolAddress((void**)&B,     g_B);
    cudaGetSymbolAddress((void**)&fh,    g_fh);
    cudaGetSymbolAddress((void**)&ft,    g_ft);
    cudaGetSymbolAddress((void**)&fr,    g_fr);
    cudaGetSymbolAddress((void**)&fcnt,  g_fcnt);
    cudaGetSymbolAddress((void**)&acnt,  g_acnt);
    cudaGetSymbolAddress((void**)&aptr,  g_aptr);
    cudaGetSymbolAddress((void**)&acur,  g_acur);
    cudaGetSymbolAddress((void**)&acolS, g_acol);
    cudaGetSymbolAddress((void**)&avalS, g_aval);
    cudaGetSymbolAddress((void**)&bsums, g_bsums);

    const int nbA = (NUI + 1023) / 1024;   // 147

    // Launch order keeps k_rgat<1> as the 5th launch (ncu -s 5 capture).
    cudaMemsetAsync(sA, 0, (size_t)NENT * D * sizeof(float));      // 1
    cudaMemsetAsync(sB, 0, (size_t)NITEM * D * sizeof(float));     // 2
    cudaMemsetAsync(acnt, 0, NUI * sizeof(int));                   // 3
    k_norms<<<NENT / 32, 256>>>(eE, nrm1);                         // 4

    // ---- RGAT hop 1 (all edges)
    k_rgat<1><<<NEDGE / 32, 256>>>(eE, rE, eh, et, ety, nrm1, nullptr, sA);  // 5
    k_invn<<<NENT / 8, 256>>>(sA, invn);                           // 6

    // ---- filter edges (head < NITEM) + RGAT hop 2 on compact list
    cudaMemsetAsync(fcnt, 0, sizeof(int));                         // 7
    k_filter<<<(NEDGE + 255) / 256, 256>>>(eh, et, ety, fcnt, fh, ft, fr);   // 8
    k_rgat<2><<<NEDGE / 32, 256>>>(sA, rE, fh, ft, fr, invn, fcnt, sB);      // 9

    // ---- adj CSR build
    k_hist<<<(NNZ + 255) / 256, 256>>>(arow, NNZ, acnt);
    k_blocksum<<<nbA, 1024>>>(acnt, NUI, bsums);
    k_scanbsums<<<1, 1024>>>(bsums, nbA);
    k_scanblock<<<nbA, 1024>>>(acnt, NUI, bsums, aptr, acur);
    k_ascatter<<<(NNZ + 255) / 256, 256>>>(arow, acol, aval, acur, acolS, avalS);

    // ---- embeds + total init (ent_res = 0.25*e0 + 0.5*n1 + n2), sB norm fused
    k_embeds<<<NUI / 8, 256>>>(uE, eE, sA, invn, sB, A, out);

    // ---- GCN layers via CSR, out += fused
    k_spmm<1><<<NUI / 8, 256>>>(A, aptr, acolS, avalS, B, out);
    k_spmm<0><<<NUI / 8, 256>>>(B, aptr, acolS, avalS, nullptr, out);
}

// round 8
// speedup vs baseline: 2.2545x; 1.3186x over previous
#include <cuda_runtime.h>
#include <math.h>

#define NUSER 100000
#define NITEM 50000
#define NENT  200000
#define NREL  32
#define D     64
#define NEDGE 500000
#define NNZ   2000000
#define NUI   (NUSER + NITEM)
#define FULL  0xffffffffu

// ---------------- scratch (device globals; no runtime allocation) ----------
__device__ float g_sA[NENT * D];     // hop1 sums (raw, unnormalized)
__device__ float g_sB[NITEM * D];    // hop2 sums (only item rows needed)
__device__ float g_nrm1[NENT];       // ||eE_i||^2
__device__ float g_relC[NREL];       // ||rE_r||^2
__device__ float g_invn[NENT];       // 1/||sA_i|| (0 if zero row)
__device__ float g_A[NUI * D];       // embeds
__device__ float g_B[NUI * D];       // gcn intermediate
// hop2 filtered edges (head < NITEM)
__device__ int   g_fh [NEDGE];
__device__ int   g_ft [NEDGE];
__device__ int   g_fr [NEDGE];
// hop1 filtered edges (head needed)
__device__ int   g_h1 [NEDGE];
__device__ int   g_t1 [NEDGE];
__device__ int   g_r1 [NEDGE];
// flag[NENT] + counters: [NENT]=fcnt(hop2), [NENT+1]=n1cnt(hop1)
__device__ int   g_flag[NENT + 2];
// adj CSR
__device__ int   g_acnt[NUI];
__device__ int   g_aptr[NUI + 1];
__device__ int   g_acur[NUI];
__device__ int   g_acol[NNZ];
__device__ float g_aval[NNZ];
__device__ int   g_bsums[1024];

// ---------------- helpers ----------------
__device__ __forceinline__ float wredsum(float v) {
    v += __shfl_xor_sync(FULL, v, 16);
    v += __shfl_xor_sync(FULL, v, 8);
    v += __shfl_xor_sync(FULL, v, 4);
    v += __shfl_xor_sync(FULL, v, 2);
    v += __shfl_xor_sync(FULL, v, 1);
    return v;
}
__device__ __forceinline__ float r8sum(float v) {   // 8-lane groups
    v += __shfl_xor_sync(FULL, v, 4);
    v += __shfl_xor_sync(FULL, v, 2);
    v += __shfl_xor_sync(FULL, v, 1);
    return v;
}
__device__ __forceinline__ float dot4(float4 a, float4 b) {
    return a.x * b.x + a.y * b.y + a.z * b.z + a.w * b.w;
}
__device__ __forceinline__ float tanhf_fast(float x) {  // x >= 0
    if (x < 1e-4f) return x;
    float e = __expf(2.0f * x);
    return __fdividef(e - 1.0f, e + 1.0f);
}
__device__ __forceinline__ float atanhf_fast(float x) { // 0 <= x <= 1-1e-5
    return 0.5f * __logf(__fdividef(1.0f + x, 1.0f - x));
}

// ---------------- per-row squared norms: 4 rows/warp -----------------------
__global__ void __launch_bounds__(256) k_norms(const float* __restrict__ ent,
                                               float* __restrict__ nrm)
{
    int lane = threadIdx.x & 31;
    int g = lane >> 3, sl = lane & 7;
    int row = ((blockIdx.x * blockDim.x + threadIdx.x) >> 5) * 4 + g;  // exact grid
    const float4* e4 = reinterpret_cast<const float4*>(ent);
    float4 a = e4[(size_t)row * 16 + sl * 2];
    float4 b = e4[(size_t)row * 16 + sl * 2 + 1];
    float s = r8sum(dot4(a, a) + dot4(b, b));
    if (sl == 0) nrm[row] = s;
}

// ---------------- inverse norms of sA (no buffer rewrite) ------------------
__global__ void __launch_bounds__(256) k_invn(const float* __restrict__ buf,
                                              float* __restrict__ invn)
{
    int w = (blockIdx.x * blockDim.x + threadIdx.x) >> 5;
    int lane = threadIdx.x & 31;
    const float2* b2 = reinterpret_cast<const float2*>(buf);
    float2 v = b2[(size_t)w * 32 + lane];
    float s = wredsum(v.x * v.x + v.y * v.y);
    if (lane == 0)
        invn[w] = (s > 0.0f) ? __fdividef(1.0f, fmaxf(sqrtf(s), 1e-12f)) : 0.0f;
}

// ---------------- hop2 filter: head < NITEM, warp-aggregated ---------------
__global__ void k_filter2(const int* __restrict__ head, const int* __restrict__ tail,
                          const int* __restrict__ etype, int* __restrict__ cnt,
                          int* __restrict__ fh, int* __restrict__ ft, int* __restrict__ fr)
{
    int i = blockIdx.x * blockDim.x + threadIdx.x;
    int lane = threadIdx.x & 31;
    int h = 0; bool keep = false;
    if (i < NEDGE) { h = head[i]; keep = (h < NITEM); }
    unsigned m = __ballot_sync(FULL, keep);
    int n = __popc(m);
    int base = 0;
    if (lane == 0 && n) base = atomicAdd(cnt, n);
    base = __shfl_sync(FULL, base, 0);
    if (keep) {
        int p = base + __popc(m & ((1u << lane) - 1));
        fh[p] = h;
        ft[p] = tail[i];
        fr[p] = etype[i] - 1;
    }
}

// ---------------- flag tails of hop2 edges ---------------------------------
__global__ void k_flagtails(const int* __restrict__ ft, const int* __restrict__ cnt,
                            int* __restrict__ flag)
{
    int i = blockIdx.x * blockDim.x + threadIdx.x;
    if (i < *cnt) flag[ft[i]] = 1;
}

// ---------------- hop1 filter: head needed, warp-aggregated ----------------
__global__ void k_filter1(const int* __restrict__ head, const int* __restrict__ tail,
                          const int* __restrict__ etype, const int* __restrict__ flag,
                          int* __restrict__ cnt,
                          int* __restrict__ oh, int* __restrict__ ot, int* __restrict__ orr)
{
    int i = blockIdx.x * blockDim.x + threadIdx.x;
    int lane = threadIdx.x & 31;
    int h = 0; bool keep = false;
    if (i < NEDGE) { h = head[i]; keep = (h < NITEM) || (flag[h] != 0); }
    unsigned m = __ballot_sync(FULL, keep);
    int n = __popc(m);
    int base = 0;
    if (lane == 0 && n) base = atomicAdd(cnt, n);
    base = __shfl_sync(FULL, base, 0);
    if (keep) {
        int p = base + __popc(m & ((1u << lane) - 1));
        oh[p] = h;
        ot[p] = tail[i];
        orr[p] = etype[i] - 1;
    }
}

// ---------------- RGAT: 4 edges per warp (8-lane groups), no smem ----------
// HOP==1: sc = raw squared norms of input rows
// HOP==2: sc = 1/||row||; input rows raw; normalization folded into scalars
template <int HOP>
__global__ void __launch_bounds__(256) k_rgat(
    const float* __restrict__ entP, const float* __restrict__ rel,
    const float* __restrict__ relC,
    const int* __restrict__ head, const int* __restrict__ tail,
    const int* __restrict__ rtype, const float* __restrict__ sc,
    const int* __restrict__ nlim,
    float* __restrict__ sums)
{
    int lane = threadIdx.x & 31;
    int g  = lane >> 3;
    int sl = lane & 7;
    int e = ((blockIdx.x * blockDim.x + threadIdx.x) >> 5) * 4 + g;
    if (e >= *nlim) return;

    int h = head[e];
    int t = tail[e];
    int r = rtype[e];

    const float4* e4 = reinterpret_cast<const float4*>(entP);
    const float4* r4 = reinterpret_cast<const float4*>(rel);
    float4 he0 = e4[(size_t)h * 16 + sl * 2];
    float4 he1 = e4[(size_t)h * 16 + sl * 2 + 1];
    float4 te0 = e4[(size_t)t * 16 + sl * 2];
    float4 te1 = e4[(size_t)t * 16 + sl * 2 + 1];
    float4 re0 = __ldg(r4 + r * 16 + sl * 2);
    float4 re1 = __ldg(r4 + r * 16 + sl * 2 + 1);

    float A, B, ih = 1.0f, it = 1.0f;
    if (HOP == 1) {
        A = sc[h];
        B = sc[t];
    } else {
        ih = sc[h]; it = sc[t];
        A = (ih > 0.0f) ? 1.0f : 0.0f;
        B = (it > 0.0f) ? 1.0f : 0.0f;
    }
    float C = __ldg(relC + r);
    float P = r8sum(dot4(he0, te0) + dot4(he1, te1));
    float Q = r8sum(dot4(he0, re0) + dot4(he1, re1));
    float R = r8sum(dot4(te0, re0) + dot4(te1, re1));
    if (HOP == 2) { P *= ih * it; Q *= ih; R *= it; }

    const float MINN = 1e-15f;
    // hh = expmap0(he) = alpha * he
    float nhe   = fmaxf(sqrtf(A), MINN);
    float alpha = __fdividef(tanhf_fast(nhe), nhe);
    float sq    = alpha * alpha * A;
    float omq   = 1.0f - sq;
    float lamden = fmaxf(omq, MINN);
    float lam   = __fdividef(2.0f, lamden);
    // ht = expmap(te, hh) = p1*he + p2*te
    float nte = fmaxf(sqrtf(B), MINN);
    float at  = __fdividef(tanhf_fast(0.5f * lam * nte), nte);
    float y2t = at * at * B;
    float xyt = at * alpha * P;
    float dent = fmaxf(1.0f + 2.0f * xyt + sq * y2t, MINN);
    float p1 = __fdividef((1.0f + 2.0f * xyt + y2t) * alpha, dent);
    float p2 = __fdividef(omq * at, dent);
    // hr = expmap(re, hh) = q1*he + q3*re
    float nre = fmaxf(sqrtf(C), MINN);
    float ar  = __fdividef(tanhf_fast(0.5f * lam * nre), nre);
    float y2r = ar * ar * C;
    float xyr = ar * alpha * Q;
    float denr = fmaxf(1.0f + 2.0f * xyr + sq * y2r, MINN);
    float q1 = __fdividef((1.0f + 2.0f * xyr + y2r) * alpha, denr);
    float q3 = __fdividef(omq * ar, denr);
    // scalar dots
    float sht = p1 * p1 * A + 2.0f * p1 * p2 * P + p2 * p2 * B;
    float shr = q1 * q1 * A + 2.0f * q1 * q3 * Q + q3 * q3 * C;
    float dhh = p1 * q1 * A + p1 * q3 * Q + p2 * q1 * P + p2 * q3 * R;
    // m = mobius_add(ht, hr) = m1*he + m2*te + m3*re
    float denm = fmaxf(1.0f + 2.0f * dhh + sht * shr, MINN);
    float f1 = __fdividef(1.0f + 2.0f * dhh + shr, denm);
    float f2 = __fdividef(1.0f - sht, denm);
    float m1 = f1 * p1 + f2 * q1;
    float m2 = f1 * p2;
    float m3 = f2 * q3;
    float sm = m1 * m1 * A + m2 * m2 * B + m3 * m3 * C
             + 2.0f * (m1 * m2 * P + m1 * m3 * Q + m2 * m3 * R);
    sm = fmaxf(sm, 0.0f);
    // project
    float nm = fmaxf(sqrtf(sm), MINN);
    float scale = (nm > 0.999f) ? __fdividef(0.999f, nm) : 1.0f;
    float sqres = sm * scale * scale;
    // logmap: sub = u1*he + u2*te + u3*re
    float dhres = scale * alpha * (m1 * A + m2 * P + m3 * Q);
    float xy = -dhres;
    float denl = fmaxf(1.0f + 2.0f * xy + sq * sqres, MINN);
    float gg1 = __fdividef(1.0f + 2.0f * xy + sqres, denl);
    float gg2 = __fdividef(omq, denl);
    float u1 = -gg1 * alpha + gg2 * scale * m1;
    float u2 = gg2 * scale * m2;
    float u3 = gg2 * scale * m3;
    float ssub = u1 * u1 * A + u2 * u2 * B + u3 * u3 * C
               + 2.0f * (u1 * u2 * P + u1 * u3 * Q + u2 * u3 * R);
    ssub = fmaxf(ssub, 0.0f);
    float nsub = fmaxf(sqrtf(ssub), MINN);
    float coef = lamden * __fdividef(atanhf_fast(fminf(nsub, 1.0f - 1e-5f)), nsub);
    // ricci coefficient (normalized te)
    float stere = B + 2.0f * R + C;
    float epst = __fdividef(1e-7f, fmaxf(sqrtf(stere), 1e-12f));

    float c1 = coef * u1;
    float c2 = coef * u2 + epst;
    float c3 = coef * u3 + epst;
    if (HOP == 2) { c1 *= ih; c2 *= it; }

    float4 o0, o1;
    o0.x = fmaxf(c1 * he0.x + c2 * te0.x + c3 * re0.x, 0.0f);
    o0.y = fmaxf(c1 * he0.y + c2 * te0.y + c3 * re0.y, 0.0f);
    o0.z = fmaxf(c1 * he0.z + c2 * te0.z + c3 * re0.z, 0.0f);
    o0.w = fmaxf(c1 * he0.w + c2 * te0.w + c3 * re0.w, 0.0f);
    o1.x = fmaxf(c1 * he1.x + c2 * te1.x + c3 * re1.x, 0.0f);
    o1.y = fmaxf(c1 * he1.y + c2 * te1.y + c3 * re1.y, 0.0f);
    o1.z = fmaxf(c1 * he1.z + c2 * te1.z + c3 * re1.z, 0.0f);
    o1.w = fmaxf(c1 * he1.w + c2 * te1.w + c3 * re1.w, 0.0f);

    float4* base = reinterpret_cast<float4*>(sums + (size_t)h * D + sl * 8);
    atomicAdd(base, o0);
    atomicAdd(base + 1, o1);
}

// ---------------- embeds: warp per row; fuses sB l2norm + residual ---------
__global__ void __launch_bounds__(256) k_embeds(
    const float* __restrict__ u, const float* __restrict__ e0,
    const float* __restrict__ sA, const float* __restrict__ invnA,
    const float* __restrict__ sB,
    float* __restrict__ Aout, float* __restrict__ out)
{
    int w = (blockIdx.x * blockDim.x + threadIdx.x) >> 5;   // row, exact grid
    int lane = threadIdx.x & 31;
    size_t o = (size_t)w * 32 + lane;
    float2 v;
    if (w < NUSER) {
        v = reinterpret_cast<const float2*>(u)[o];
    } else {
        int j = w - NUSER;
        size_t jo = (size_t)j * 32 + lane;
        float2 a = reinterpret_cast<const float2*>(e0)[jo];
        float2 b = reinterpret_cast<const float2*>(sA)[jo];
        float2 c = reinterpret_cast<const float2*>(sB)[jo];
        float ia = invnA[j];
        float s = wredsum(c.x * c.x + c.y * c.y);
        float ic = __fdividef(1.0f, fmaxf(sqrtf(s), 1e-12f));
        v.x = 0.25f * a.x + 0.5f * ia * b.x + ic * c.x;
        v.y = 0.25f * a.y + 0.5f * ia * b.y + ic * c.y;
    }
    reinterpret_cast<float2*>(Aout)[o] = v;
    reinterpret_cast<float2*>(out)[o] = v;
}

// ---------------- adj CSR build --------------------------------------------
__global__ void k_hist(const int* __restrict__ key, int n, int* __restrict__ cnt) {
    int i = blockIdx.x * blockDim.x + threadIdx.x;
    if (i < n) atomicAdd(&cnt[key[i]], 1);
}
__global__ void k_blocksum(const int* __restrict__ cnt, int n, int* __restrict__ bs) {
    __shared__ int sh[1024];
    int i = blockIdx.x * 1024 + threadIdx.x;
    sh[threadIdx.x] = (i < n) ? cnt[i] : 0;
    __syncthreads();
    for (int s = 512; s > 0; s >>= 1) {
        if (threadIdx.x < s) sh[threadIdx.x] += sh[threadIdx.x + s];
        __syncthreads();
    }
    if (threadIdx.x == 0) bs[blockIdx.x] = sh[0];
}
__global__ void k_scanbsums(int* __restrict__ bs, int nb) {
    __shared__ int sh[1024];
    int v = (threadIdx.x < nb) ? bs[threadIdx.x] : 0;
    sh[threadIdx.x] = v;
    __syncthreads();
    for (int off = 1; off < 1024; off <<= 1) {
        int t = (threadIdx.x >= off) ? sh[threadIdx.x - off] : 0;
        __syncthreads();
        sh[threadIdx.x] += t;
        __syncthreads();
    }
    if (threadIdx.x < nb) bs[threadIdx.x] = sh[threadIdx.x] - v;  // exclusive
}
__global__ void k_scanblock(const int* __restrict__ cnt, int n,
                            const int* __restrict__ bs,
                            int* __restrict__ ptr, int* __restrict__ cur) {
    __shared__ int sh[1024];
    int i = blockIdx.x * 1024 + threadIdx.x;
    int v = (i < n) ? cnt[i] : 0;
    sh[threadIdx.x] = v;
    __syncthreads();
    for (int off = 1; off < 1024; off <<= 1) {
        int t = (threadIdx.x >= off) ? sh[threadIdx.x - off] : 0;
        __syncthreads();
        sh[threadIdx.x] += t;
        __syncthreads();
    }
    int excl = sh[threadIdx.x] - v + bs[blockIdx.x];
    if (i < n) { ptr[i] = excl; cur[i] = excl; }
    if (i == n - 1) ptr[n] = excl + v;
}
__global__ void k_ascatter(const int* __restrict__ row, const int* __restrict__ col,
                           const float* __restrict__ val,
                           int* __restrict__ cur,
                           int* __restrict__ ocol, float* __restrict__ oval) {
    int i = blockIdx.x * blockDim.x + threadIdx.x;
    if (i >= NNZ) return;
    int pos = atomicAdd(&cur[row[i]], 1);
    ocol[pos] = col[i];
    oval[pos] = val[i];
}

// ---------------- CSR SpMM: 2 rows/warp, float4, fused out += --------------
template <int STORE>
__global__ void __launch_bounds__(256) k_spmm(
    const float* __restrict__ curbuf, const int* __restrict__ ptr,
    const int* __restrict__ cols, const float* __restrict__ vals,
    float* __restrict__ nxt, float* __restrict__ out)
{
    int lane = threadIdx.x & 31;
    int g  = lane >> 4;
    int sl = lane & 15;
    int row = ((blockIdx.x * blockDim.x + threadIdx.x) >> 5) * 2 + g;  // exact grid
    int beg = ptr[row], end = ptr[row + 1];
    const float4* cb = reinterpret_cast<const float4*>(curbuf);
    float4 acc = make_float4(0.0f, 0.0f, 0.0f, 0.0f);
    int j = beg;
    for (; j + 4 <= end; j += 4) {
        #pragma unroll
        for (int u = 0; u < 4; u++) {
            int   cc = cols[j + u];
            float vv = vals[j + u];
            float4 x = cb[(size_t)cc * 16 + sl];
            acc.x = fmaf(vv, x.x, acc.x);
            acc.y = fmaf(vv, x.y, acc.y);
            acc.z = fmaf(vv, x.z, acc.z);
            acc.w = fmaf(vv, x.w, acc.w);
        }
    }
    for (; j < end; j++) {
        int cc = cols[j]; float vv = vals[j];
        float4 x = cb[(size_t)cc * 16 + sl];
        acc.x = fmaf(vv, x.x, acc.x);
        acc.y = fmaf(vv, x.y, acc.y);
        acc.z = fmaf(vv, x.z, acc.z);
        acc.w = fmaf(vv, x.w, acc.w);
    }
    size_t o = (size_t)row * 16 + sl;
    if (STORE) reinterpret_cast<float4*>(nxt)[o] = acc;
    float4 ov = reinterpret_cast<float4*>(out)[o];
    ov.x += acc.x; ov.y += acc.y; ov.z += acc.z; ov.w += acc.w;
    reinterpret_cast<float4*>(out)[o] = ov;
}

// ---------------- launch ---------------------------------------------------
extern "C" void kernel_launch(void* const* d_in, const int* in_sizes, int n_in,
                              void* d_out, int out_size)
{
    const float* uE   = (const float*)d_in[0];
    const float* eE   = (const float*)d_in[1];
    const float* rE   = (const float*)d_in[2];
    const float* aval = (const float*)d_in[3];
    const int*   eh   = (const int*)d_in[4];
    const int*   et   = (const int*)d_in[5];
    const int*   ety  = (const int*)d_in[6];
    const int*   arow = (const int*)d_in[7];
    const int*   acol = (const int*)d_in[8];
    float* out = (float*)d_out;

    float *sA, *sB, *nrm1, *relC, *invn, *A, *B, *avalS;
    int *fh, *ft, *fr, *h1, *t1, *r1, *flag;
    int *acnt, *aptr, *acur, *acolS, *bsums;
    cudaGetSymbolAddress((void**)&sA,    g_sA);
    cudaGetSymbolAddress((void**)&sB,    g_sB);
    cudaGetSymbolAddress((void**)&nrm1,  g_nrm1);
    cudaGetSymbolAddress((void**)&relC,  g_relC);
    cudaGetSymbolAddress((void**)&invn,  g_invn);
    cudaGetSymbolAddress((void**)&A,     g_A);
    cudaGetSymbolAddress((void**)&B,     g_B);
    cudaGetSymbolAddress((void**)&fh,    g_fh);
    cudaGetSymbolAddress((void**)&ft,    g_ft);
    cudaGetSymbolAddress((void**)&fr,    g_fr);
    cudaGetSymbolAddress((void**)&h1,    g_h1);
    cudaGetSymbolAddress((void**)&t1,    g_t1);
    cudaGetSymbolAddress((void**)&r1,    g_r1);
    cudaGetSymbolAddress((void**)&flag,  g_flag);
    cudaGetSymbolAddress((void**)&acnt,  g_acnt);
    cudaGetSymbolAddress((void**)&aptr,  g_aptr);
    cudaGetSymbolAddress((void**)&acur,  g_acur);
    cudaGetSymbolAddress((void**)&acolS, g_acol);
    cudaGetSymbolAddress((void**)&avalS, g_aval);
    cudaGetSymbolAddress((void**)&bsums, g_bsums);

    int* fcnt  = flag + NENT;      // hop2 edge count
    int* n1cnt = flag + NENT + 1;  // hop1 edge count

    const int nbA = (NUI + 1023) / 1024;   // 147

    cudaMemsetAsync(sA, 0, (size_t)NENT * D * sizeof(float));
    cudaMemsetAsync(sB, 0, (size_t)NITEM * D * sizeof(float));
    cudaMemsetAsync(acnt, 0, NUI * sizeof(int));
    cudaMemsetAsync(flag, 0, (NENT + 2) * sizeof(int));

    // ---- edge filters (hop2 first; its tails define hop1's needed heads)
    k_filter2<<<(NEDGE + 255) / 256, 256>>>(eh, et, ety, fcnt, fh, ft, fr);
    k_flagtails<<<(NEDGE + 255) / 256, 256>>>(ft, fcnt, flag);
    k_filter1<<<(NEDGE + 255) / 256, 256>>>(eh, et, ety, flag, n1cnt, h1, t1, r1);

    // ---- norms
    k_norms<<<NENT / 32, 256>>>(eE, nrm1);
    k_norms<<<1, 256>>>(rE, relC);          // 32 relation rows

    // ---- RGAT hop 1 (filtered edges)
    k_rgat<1><<<NEDGE / 32, 256>>>(eE, rE, relC, h1, t1, r1, nrm1, n1cnt, sA);
    k_invn<<<NENT / 8, 256>>>(sA, invn);
    // ---- RGAT hop 2 (item-head edges)
    k_rgat<2><<<NEDGE / 32, 256>>>(sA, rE, relC, fh, ft, fr, invn, fcnt, sB);

    // ---- adj CSR build
    k_hist<<<(NNZ + 255) / 256, 256>>>(arow, NNZ, acnt);
    k_blocksum<<<nbA, 1024>>>(acnt, NUI, bsums);
    k_scanbsums<<<1, 1024>>>(bsums, nbA);
    k_scanblock<<<nbA, 1024>>>(acnt, NUI, bsums, aptr, acur);
    k_ascatter<<<(NNZ + 255) / 256, 256>>>(arow, acol, aval, acur, acolS, avalS);

    // ---- embeds + total init (ent_res = 0.25*e0 + 0.5*n1 + n2), sB norm fused
    k_embeds<<<NUI / 8, 256>>>(uE, eE, sA, invn, sB, A, out);

    // ---- GCN layers via CSR, out += fused
    k_spmm<1><<<NUI / 16, 256>>>(A, aptr, acolS, avalS, B, out);
    k_spmm<0><<<NUI / 16, 256>>>(B, aptr, acolS, avalS, nullptr, out);
}